// round 1
// baseline (speedup 1.0000x reference)
#include <cuda_runtime.h>
#include <cuda_bf16.h>
#include <cstdint>

#define NA 4096
#define NB 4096
#define DD 256
#define HH 4
#define DKK 64

#define BR 32   // query rows per CTA
#define BC 64   // key cols per tile

// ---------------- device scratch (no allocations allowed) ----------------
__device__ __nv_bfloat16 g_Qhi[NA * DD];
__device__ __nv_bfloat16 g_Qlo[NA * DD];
__device__ __nv_bfloat16 g_Khi[NB * DD];
__device__ __nv_bfloat16 g_Klo[NB * DD];
__device__ __nv_bfloat16 g_Vhi[NB * DD];
__device__ __nv_bfloat16 g_Vlo[NB * DD];
__device__ int g_mask_kind; // 0 = u8/bool, 1 = int32, 2 = float32

// ---------------- mask dtype detector ----------------
__global__ void detect_mask_kind(const unsigned int* __restrict__ m) {
    __shared__ int s_i32, s_f32;
    if (threadIdx.x == 0) { s_i32 = 1; s_f32 = 1; }
    __syncthreads();
    int ok_i = 1, ok_f = 1;
    for (int i = threadIdx.x; i < 4096; i += 256) {
        unsigned v = m[i];
        ok_i &= (v <= 1u);
        ok_f &= (v == 0u || v == 0x3F800000u);
    }
    if (!ok_i) atomicAnd(&s_i32, 0);
    if (!ok_f) atomicAnd(&s_f32, 0);
    __syncthreads();
    if (threadIdx.x == 0)
        g_mask_kind = s_i32 ? 1 : (s_f32 ? 2 : 0);
}

// ---------------- projection GEMMs: out = X @ W^T, split to bf16 hi/lo ----------------
// grid: (N/64, M/64, 3), block: 256 threads (16x16), 4x4 micro-tile
__global__ void __launch_bounds__(256) proj_kernel(
    const float* __restrict__ a_z, const float* __restrict__ bv_z,
    const float* __restrict__ Wq, const float* __restrict__ Wk, const float* __restrict__ Wv)
{
    const int mat = blockIdx.z;
    const float* X = (mat == 0) ? a_z : bv_z;
    const float* W = (mat == 0) ? Wq : (mat == 1 ? Wk : Wv);
    __nv_bfloat16* Ohi = (mat == 0) ? g_Qhi : (mat == 1 ? g_Khi : g_Vhi);
    __nv_bfloat16* Olo = (mat == 0) ? g_Qlo : (mat == 1 ? g_Klo : g_Vlo);

    __shared__ float As[64][17];
    __shared__ float Bs[64][17];

    const int tid = threadIdx.x;
    const int tx = tid & 15, ty = tid >> 4;
    const int m0 = blockIdx.y * 64, n0 = blockIdx.x * 64;

    float acc[4][4];
#pragma unroll
    for (int i = 0; i < 4; i++)
#pragma unroll
        for (int j = 0; j < 4; j++) acc[i][j] = 0.f;

    for (int k0 = 0; k0 < DD; k0 += 16) {
#pragma unroll
        for (int i = tid; i < 64 * 16; i += 256) {
            int r = i >> 4, c = i & 15;
            As[r][c] = X[(m0 + r) * DD + k0 + c];
        }
#pragma unroll
        for (int i = tid; i < 64 * 16; i += 256) {
            int r = i >> 4, c = i & 15;
            Bs[r][c] = W[(n0 + r) * DD + k0 + c];
        }
        __syncthreads();
#pragma unroll
        for (int kk = 0; kk < 16; kk++) {
            float a[4], b[4];
#pragma unroll
            for (int i = 0; i < 4; i++) a[i] = As[ty * 4 + i][kk];
#pragma unroll
            for (int j = 0; j < 4; j++) b[j] = Bs[tx * 4 + j][kk];
#pragma unroll
            for (int i = 0; i < 4; i++)
#pragma unroll
                for (int j = 0; j < 4; j++) acc[i][j] += a[i] * b[j];
        }
        __syncthreads();
    }

#pragma unroll
    for (int i = 0; i < 4; i++)
#pragma unroll
        for (int j = 0; j < 4; j++) {
            float x = acc[i][j];
            int row = m0 + ty * 4 + i, col = n0 + tx * 4 + j;
            __nv_bfloat16 hi = __float2bfloat16(x);
            __nv_bfloat16 lo = __float2bfloat16(x - __bfloat162float(hi));
            Ohi[row * DD + col] = hi;
            Olo[row * DD + col] = lo;
        }
}

// ---------------- attention ----------------
__device__ __forceinline__ void mma16816(float* c, const unsigned* a, const unsigned* b) {
    asm volatile(
        "mma.sync.aligned.m16n8k16.row.col.f32.bf16.bf16.f32 "
        "{%0,%1,%2,%3}, {%4,%5,%6,%7}, {%8,%9}, {%0,%1,%2,%3};\n"
        : "+f"(c[0]), "+f"(c[1]), "+f"(c[2]), "+f"(c[3])
        : "r"(a[0]), "r"(a[1]), "r"(a[2]), "r"(a[3]), "r"(b[0]), "r"(b[1]));
}

__device__ __forceinline__ void cvt_pack(float x0, float x1, unsigned& hi, unsigned& lo) {
    __nv_bfloat16 h0 = __float2bfloat16(x0), h1 = __float2bfloat16(x1);
    __nv_bfloat16 l0 = __float2bfloat16(x0 - __bfloat162float(h0));
    __nv_bfloat16 l1 = __float2bfloat16(x1 - __bfloat162float(h1));
    hi = ((unsigned)__bfloat16_as_ushort(h1) << 16) | (unsigned)__bfloat16_as_ushort(h0);
    lo = ((unsigned)__bfloat16_as_ushort(l1) << 16) | (unsigned)__bfloat16_as_ushort(l0);
}

// smem layout (bytes)
#define QROW 260    // 256 + 4 pad (bf16 elems); 520B row = 130 words, %32 = 2
#define VROW 68     // 64 + 4 pad
#define WROW 66
#define MROW 68
#define OFF_QHI 0
#define OFF_QLO (OFF_QHI + BR * QROW * 2)                 // 16640
#define OFF_KHI (OFF_QLO + BR * QROW * 2)                 // 33280
#define OFF_KLO (OFF_KHI + BC * QROW * 2)                 // 66560
#define OFF_VHI (OFF_KLO + BC * QROW * 2)                 // 99840
#define OFF_VLO (OFF_VHI + DD * VROW * 2)                 // 134656
#define OFF_W   (OFF_VLO + DD * VROW * 2)                 // 169472
#define OFF_M   (OFF_W + BR * WROW * 4)                   // 177920
#define OFF_O   (OFF_M + BR * MROW)                       // 180096 (round to 4: 180096%4==0)
#define SMEM_BYTES (OFF_O + HH * BR * DKK * 4)            // 180096 + 32768 = 212864

__global__ void __launch_bounds__(256) attn_kernel(
    const float* __restrict__ weight, const void* __restrict__ mask_raw,
    float* __restrict__ out)
{
    extern __shared__ char sm[];
    __nv_bfloat16* q_hi = (__nv_bfloat16*)(sm + OFF_QHI);
    __nv_bfloat16* q_lo = (__nv_bfloat16*)(sm + OFF_QLO);
    __nv_bfloat16* k_hi = (__nv_bfloat16*)(sm + OFF_KHI);
    __nv_bfloat16* k_lo = (__nv_bfloat16*)(sm + OFF_KLO);
    __nv_bfloat16* vt_hi = (__nv_bfloat16*)(sm + OFF_VHI);
    __nv_bfloat16* vt_lo = (__nv_bfloat16*)(sm + OFF_VLO);
    float* w_s = (float*)(sm + OFF_W);
    uint8_t* m_s = (uint8_t*)(sm + OFF_M);
    float* o_s = (float*)(sm + OFF_O);   // [h][32][64]

    const int tid = threadIdx.x;
    const int wid = tid >> 5, lane = tid & 31;
    const int h = wid >> 1, rsel = wid & 1;
    const int g = lane >> 2, t = lane & 3;
    const int a0 = blockIdx.x * BR;
    const int qrow0 = rsel * 16 + g;     // local row for c0/c1; +8 for c2/c3
    const int kind = g_mask_kind;

    // load Q tile (rows a0..a0+31, all 256 channels), vectorized 2x bf16
    for (int i = tid; i < BR * 128; i += 256) {
        int r = i >> 7, c2 = (i & 127) * 2;
        *(unsigned*)&q_hi[r * QROW + c2] = *(const unsigned*)&g_Qhi[(a0 + r) * DD + c2];
        *(unsigned*)&q_lo[r * QROW + c2] = *(const unsigned*)&g_Qlo[(a0 + r) * DD + c2];
    }

    float o[8][4];
#pragma unroll
    for (int nt = 0; nt < 8; nt++)
#pragma unroll
        for (int e = 0; e < 4; e++) o[nt][e] = 0.f;
    float lsum0 = 0.f, lsum1 = 0.f;

    for (int bt = 0; bt < NB / BC; bt++) {
        const int b0 = bt * BC;
        __syncthreads();
        // K tile [64][256] hi/lo
        for (int i = tid; i < BC * 128; i += 256) {
            int r = i >> 7, c2 = (i & 127) * 2;
            *(unsigned*)&k_hi[r * QROW + c2] = *(const unsigned*)&g_Khi[(b0 + r) * DD + c2];
            *(unsigned*)&k_lo[r * QROW + c2] = *(const unsigned*)&g_Klo[(b0 + r) * DD + c2];
        }
        // V tile transposed into [chan 256][b 64]
        for (int i = tid; i < BC * 128; i += 256) {
            int r = i >> 7, c2 = (i & 127) * 2;
            unsigned vh = *(const unsigned*)&g_Vhi[(b0 + r) * DD + c2];
            unsigned vl = *(const unsigned*)&g_Vlo[(b0 + r) * DD + c2];
            vt_hi[c2 * VROW + r] = __ushort_as_bfloat16((unsigned short)(vh & 0xFFFF));
            vt_hi[(c2 + 1) * VROW + r] = __ushort_as_bfloat16((unsigned short)(vh >> 16));
            vt_lo[c2 * VROW + r] = __ushort_as_bfloat16((unsigned short)(vl & 0xFFFF));
            vt_lo[(c2 + 1) * VROW + r] = __ushort_as_bfloat16((unsigned short)(vl >> 16));
        }
        // weight + mask tiles
        for (int i = tid; i < BR * BC; i += 256) {
            int r = i >> 6, c = i & 63;
            int idx = (a0 + r) * NB + b0 + c;
            w_s[r * WROW + c] = weight[idx];
            uint8_t mv;
            if (kind == 0)      mv = ((const uint8_t*)mask_raw)[idx];
            else if (kind == 1) mv = (uint8_t)(((const int*)mask_raw)[idx] != 0);
            else                mv = (uint8_t)(((const float*)mask_raw)[idx] != 0.f);
            m_s[r * MROW + c] = mv;
        }
        __syncthreads();

        // ---- S = Q K^T (3-term bf16 split) ----
        float s[8][4];
#pragma unroll
        for (int nt = 0; nt < 8; nt++)
#pragma unroll
            for (int e = 0; e < 4; e++) s[nt][e] = 0.f;

#pragma unroll
        for (int kt = 0; kt < 4; kt++) {
            const int kb = h * DKK + kt * 16 + 2 * t;
            unsigned ah[4], al[4];
            ah[0] = *(unsigned*)&q_hi[qrow0 * QROW + kb];
            ah[1] = *(unsigned*)&q_hi[(qrow0 + 8) * QROW + kb];
            ah[2] = *(unsigned*)&q_hi[qrow0 * QROW + kb + 8];
            ah[3] = *(unsigned*)&q_hi[(qrow0 + 8) * QROW + kb + 8];
            al[0] = *(unsigned*)&q_lo[qrow0 * QROW + kb];
            al[1] = *(unsigned*)&q_lo[(qrow0 + 8) * QROW + kb];
            al[2] = *(unsigned*)&q_lo[qrow0 * QROW + kb + 8];
            al[3] = *(unsigned*)&q_lo[(qrow0 + 8) * QROW + kb + 8];
#pragma unroll
            for (int nt = 0; nt < 8; nt++) {
                const int n = nt * 8 + g;
                unsigned bh[2], bl[2];
                bh[0] = *(unsigned*)&k_hi[n * QROW + kb];
                bh[1] = *(unsigned*)&k_hi[n * QROW + kb + 8];
                bl[0] = *(unsigned*)&k_lo[n * QROW + kb];
                bl[1] = *(unsigned*)&k_lo[n * QROW + kb + 8];
                mma16816(s[nt], ah, bh);
                mma16816(s[nt], al, bh);
                mma16816(s[nt], ah, bl);
            }
        }

        // ---- mask + weight + clip + exp(s-10)  (fixed softmax max = 10) ----
#pragma unroll
        for (int nt = 0; nt < 8; nt++)
#pragma unroll
            for (int e = 0; e < 4; e++) {
                int r = qrow0 + ((e >= 2) ? 8 : 0);
                int c = nt * 8 + 2 * t + (e & 1);
                float sv = s[nt][e] * 0.125f;
                float w = w_s[r * WROW + c];
                sv = m_s[r * MROW + c] ? (sv + w) : (-10000.f + w);
                sv = fminf(fmaxf(sv, -10.f), 10.f);
                float p = __expf(sv - 10.f);
                s[nt][e] = p;
                if (e < 2) lsum0 += p; else lsum1 += p;
            }

        // ---- O += P V (3-term bf16 split), P frags from S C-frags ----
#pragma unroll
        for (int kt = 0; kt < 4; kt++) {
            unsigned ph[4], pl[4];
            cvt_pack(s[2 * kt][0], s[2 * kt][1], ph[0], pl[0]);
            cvt_pack(s[2 * kt][2], s[2 * kt][3], ph[1], pl[1]);
            cvt_pack(s[2 * kt + 1][0], s[2 * kt + 1][1], ph[2], pl[2]);
            cvt_pack(s[2 * kt + 1][2], s[2 * kt + 1][3], ph[3], pl[3]);
#pragma unroll
            for (int nt = 0; nt < 8; nt++) {
                const int vrow = h * DKK + nt * 8 + g;
                const int vcol = kt * 16 + 2 * t;
                unsigned bh[2], bl[2];
                bh[0] = *(unsigned*)&vt_hi[vrow * VROW + vcol];
                bh[1] = *(unsigned*)&vt_hi[vrow * VROW + vcol + 8];
                bl[0] = *(unsigned*)&vt_lo[vrow * VROW + vcol];
                bl[1] = *(unsigned*)&vt_lo[vrow * VROW + vcol + 8];
                mma16816(o[nt], ph, bh);
                mma16816(o[nt], pl, bh);
                mma16816(o[nt], ph, bl);
            }
        }
    }

    // reduce row sums across the 4 lanes of each quad
    lsum0 += __shfl_xor_sync(0xFFFFFFFFu, lsum0, 1);
    lsum0 += __shfl_xor_sync(0xFFFFFFFFu, lsum0, 2);
    lsum1 += __shfl_xor_sync(0xFFFFFFFFu, lsum1, 1);
    lsum1 += __shfl_xor_sync(0xFFFFFFFFu, lsum1, 2);
    const float inv0 = 0.25f / lsum0;   // 0.25 = mean over heads
    const float inv1 = 0.25f / lsum1;

    // each warp owns disjoint (h, rows) slots -> plain stores, deterministic
#pragma unroll
    for (int nt = 0; nt < 8; nt++)
#pragma unroll
        for (int e = 0; e < 4; e++) {
            int r = qrow0 + ((e >= 2) ? 8 : 0);
            int c = nt * 8 + 2 * t + (e & 1);
            o_s[((h * BR + r) << 6) + c] = o[nt][e] * ((e < 2) ? inv0 : inv1);
        }
    __syncthreads();

    // topic_align = sum over heads (inv already includes /h and /l)
    for (int i = tid; i < BR * DKK; i += 256) {
        int r = i >> 6, c = i & 63;
        float v = o_s[((0 * BR + r) << 6) + c] + o_s[((1 * BR + r) << 6) + c]
                + o_s[((2 * BR + r) << 6) + c] + o_s[((3 * BR + r) << 6) + c];
        out[(size_t)(a0 + r) * DKK + c] = v;
    }
    // influence: softmax rows sum to 1 -> mean over heads of sum over b == 1 exactly
    if (tid < BR) out[NA * DKK + a0 + tid] = 1.0f;
}

// ---------------- launch ----------------
extern "C" void kernel_launch(void* const* d_in, const int* in_sizes, int n_in,
                              void* d_out, int out_size)
{
    const float* a_z   = (const float*)d_in[0];
    const float* bv_z  = (const float*)d_in[1];
    const void*  mask  = d_in[2];
    const float* weight= (const float*)d_in[3];
    const float* Wq    = (const float*)d_in[4];
    const float* Wk    = (const float*)d_in[5];
    const float* Wv    = (const float*)d_in[6];
    float* out = (float*)d_out;

    detect_mask_kind<<<1, 256>>>((const unsigned int*)mask);
    proj_kernel<<<dim3(DD / 64, NA / 64, 3), 256>>>(a_z, bv_z, Wq, Wk, Wv);

    cudaFuncSetAttribute(attn_kernel, cudaFuncAttributeMaxDynamicSharedMemorySize, SMEM_BYTES);
    attn_kernel<<<NA / BR, 256, SMEM_BYTES>>>(weight, mask, out);
}

// round 4
// speedup vs baseline: 4.1283x; 4.1283x over previous
#include <cuda_runtime.h>
#include <cuda_bf16.h>
#include <cstdint>

#define NA 4096
#define NB 4096
#define DD 256
#define HH 4
#define DKK 64
#define BM 128          // query rows per CTA
#define BC 64           // keys per tile
#define NT (NB / BC)    // 64 tiles

// ---------------- device scratch ----------------
__device__ __nv_bfloat16 g_Qhi[HH * NA * DKK];
__device__ __nv_bfloat16 g_Qlo[HH * NA * DKK];
__device__ __nv_bfloat16 g_Khi[HH * NB * DKK];
__device__ __nv_bfloat16 g_Klo[HH * NB * DKK];
__device__ __nv_bfloat16 g_Vthi[HH * DKK * NB];  // [h][dk][token]
__device__ __nv_bfloat16 g_Vtlo[HH * DKK * NB];
__device__ float g_wm[(size_t)NA * NB];          // sanitize(weight) + (mask?0:-1e4)
__device__ float g_ctx[HH * NA * DKK];
__device__ int g_mask_kind;

// ---------------- helpers ----------------
__device__ __forceinline__ uint32_t smem_u32(const void* p) {
    uint32_t a;
    asm("{ .reg .u64 t; cvta.to.shared.u64 t, %1; cvt.u32.u64 %0, t; }" : "=r"(a) : "l"(p));
    return a;
}
__device__ __forceinline__ uint32_t sw128(uint32_t o) { return o ^ ((o >> 3) & 0x70); }

#define CP_ASYNC16(dst, src) \
    asm volatile("cp.async.cg.shared.global [%0], [%1], 16;\n" :: "r"(dst), "l"(src))
#define CP_COMMIT()  asm volatile("cp.async.commit_group;\n" ::: "memory")
#define CP_WAITG(n)  asm volatile("cp.async.wait_group %0;\n" :: "n"(n) : "memory")

#define LDSM4(r0, r1, r2, r3, a) \
    asm volatile("ldmatrix.sync.aligned.m8n8.x4.shared.b16 {%0,%1,%2,%3}, [%4];" \
                 : "=r"(r0), "=r"(r1), "=r"(r2), "=r"(r3) : "r"(a))

__device__ __forceinline__ void mma16816(float* c, const unsigned* a, const unsigned* b) {
    asm volatile(
        "mma.sync.aligned.m16n8k16.row.col.f32.bf16.bf16.f32 "
        "{%0,%1,%2,%3}, {%4,%5,%6,%7}, {%8,%9}, {%0,%1,%2,%3};\n"
        : "+f"(c[0]), "+f"(c[1]), "+f"(c[2]), "+f"(c[3])
        : "r"(a[0]), "r"(a[1]), "r"(a[2]), "r"(a[3]), "r"(b[0]), "r"(b[1]));
}

__device__ __forceinline__ void cvt_pack(float x0, float x1, unsigned& hi, unsigned& lo) {
    __nv_bfloat16 h0 = __float2bfloat16(x0), h1 = __float2bfloat16(x1);
    __nv_bfloat16 l0 = __float2bfloat16(x0 - __bfloat162float(h0));
    __nv_bfloat16 l1 = __float2bfloat16(x1 - __bfloat162float(h1));
    hi = ((unsigned)__bfloat16_as_ushort(h1) << 16) | (unsigned)__bfloat16_as_ushort(h0);
    lo = ((unsigned)__bfloat16_as_ushort(l1) << 16) | (unsigned)__bfloat16_as_ushort(l0);
}

__device__ __forceinline__ float san(float x) {
    if (isnan(x)) return 0.f;
    if (isinf(x)) return x > 0.f ? 1.f : -1.f;
    return x;
}

// ---------------- mask dtype detector ----------------
__global__ void detect_mask_kind(const unsigned int* __restrict__ m) {
    __shared__ int s_i32, s_f32;
    if (threadIdx.x == 0) { s_i32 = 1; s_f32 = 1; }
    __syncthreads();
    int ok_i = 1, ok_f = 1;
    for (int i = threadIdx.x; i < 4096; i += 256) {
        unsigned v = m[i];
        ok_i &= (v <= 1u);
        ok_f &= (v == 0u || v == 0x3F800000u);
    }
    if (!ok_i) atomicAnd(&s_i32, 0);
    if (!ok_f) atomicAnd(&s_f32, 0);
    __syncthreads();
    if (threadIdx.x == 0) g_mask_kind = s_i32 ? 1 : (s_f32 ? 2 : 0);
}

// ---------------- prep: fold mask into weight ----------------
__global__ void __launch_bounds__(256) prep_wm(const float4* __restrict__ w4,
                                               const void* __restrict__ mraw) {
    const int kind = g_mask_kind;
    const size_t n4 = (size_t)NA * NB / 4;
    size_t i = (size_t)blockIdx.x * 256 + threadIdx.x;
    const size_t stride = (size_t)gridDim.x * 256;
    for (; i < n4; i += stride) {
        float4 w = w4[i];
        w.x = san(w.x); w.y = san(w.y); w.z = san(w.z); w.w = san(w.w);
        int b0, b1, b2, b3;
        if (kind == 1) {
            int4 m = ((const int4*)mraw)[i];
            b0 = m.x != 0; b1 = m.y != 0; b2 = m.z != 0; b3 = m.w != 0;
        } else if (kind == 2) {
            float4 m = ((const float4*)mraw)[i];
            b0 = m.x != 0.f; b1 = m.y != 0.f; b2 = m.z != 0.f; b3 = m.w != 0.f;
        } else {
            uchar4 m = ((const uchar4*)mraw)[i];
            b0 = m.x != 0; b1 = m.y != 0; b2 = m.z != 0; b3 = m.w != 0;
        }
        float4 o;
        o.x = w.x + (b0 ? 0.f : -10000.f);
        o.y = w.y + (b1 ? 0.f : -10000.f);
        o.z = w.z + (b2 ? 0.f : -10000.f);
        o.w = w.w + (b3 ? 0.f : -10000.f);
        ((float4*)g_wm)[i] = o;
    }
}

// ---------------- projections: Q=a@Wq^T/8, K=b@Wk^T, Vt=(b@Wv^T)^T ----------------
__global__ void __launch_bounds__(256) proj_kernel(
    const float* __restrict__ a_z, const float* __restrict__ bv_z,
    const float* __restrict__ Wq, const float* __restrict__ Wk, const float* __restrict__ Wv)
{
    const int mat = blockIdx.z;
    const float* X = (mat == 0) ? a_z : bv_z;
    const float* W = (mat == 0) ? Wq : (mat == 1 ? Wk : Wv);

    __shared__ float As[64][17];
    __shared__ float Bs[64][17];

    const int tid = threadIdx.x;
    const int tx = tid & 15, ty = tid >> 4;
    const int m0 = blockIdx.y * 64, n0 = blockIdx.x * 64;

    float acc[4][4];
#pragma unroll
    for (int i = 0; i < 4; i++)
#pragma unroll
        for (int j = 0; j < 4; j++) acc[i][j] = 0.f;

    for (int k0 = 0; k0 < DD; k0 += 16) {
        for (int i = tid; i < 64 * 16; i += 256) {
            int r = i >> 4, c = i & 15;
            As[r][c] = san(X[(m0 + r) * DD + k0 + c]);
            Bs[r][c] = W[(n0 + r) * DD + k0 + c];
        }
        __syncthreads();
#pragma unroll
        for (int kk = 0; kk < 16; kk++) {
            float a[4], b[4];
#pragma unroll
            for (int i = 0; i < 4; i++) a[i] = As[ty * 4 + i][kk];
#pragma unroll
            for (int j = 0; j < 4; j++) b[j] = Bs[tx * 4 + j][kk];
#pragma unroll
            for (int i = 0; i < 4; i++)
#pragma unroll
                for (int j = 0; j < 4; j++) acc[i][j] += a[i] * b[j];
        }
        __syncthreads();
    }

    const float scale = (mat == 0) ? 0.125f : 1.0f;
#pragma unroll
    for (int i = 0; i < 4; i++)
#pragma unroll
        for (int j = 0; j < 4; j++) {
            float x = acc[i][j] * scale;
            int row = m0 + ty * 4 + i, col = n0 + tx * 4 + j;
            int head = col >> 6, cc = col & 63;
            __nv_bfloat16 hi = __float2bfloat16(x);
            __nv_bfloat16 lo = __float2bfloat16(x - __bfloat162float(hi));
            if (mat == 0) {
                size_t a0 = ((size_t)head * NA + row) * DKK + cc;
                g_Qhi[a0] = hi; g_Qlo[a0] = lo;
            } else if (mat == 1) {
                size_t a0 = ((size_t)head * NB + row) * DKK + cc;
                g_Khi[a0] = hi; g_Klo[a0] = lo;
            } else {
                size_t a0 = ((size_t)(head * DKK + cc)) * NB + row;
                g_Vthi[a0] = hi; g_Vtlo[a0] = lo;
            }
        }
}

// ---------------- smem layout (bytes) ----------------
#define WMP 76                                   // wm row pitch in floats (304B, 16B-aligned)
#define OFF_Q 0                                  // hi 16384 + lo 16384
#define OFF_KS(s)  (32768 + (s) * 16384)         // hi 8192 + lo 8192 per stage
#define OFF_VS(s)  (65536 + (s) * 16384)
#define OFF_WMS(s) (98304 + (s) * 38912)         // 128 * 304 per stage
#define SMEM_BYTES 176128

// ---------------- tile loader ----------------
__device__ __forceinline__ void load_tiles(uint32_t smb, int tid, int h, int a0, int bt) {
    const int s = bt & 1, b0 = bt * BC;
    for (int i = tid; i < 512; i += 256) {
        int r = i >> 3, c = i & 7;
        uint32_t sw = sw128(r * 128 + c * 16);
        CP_ASYNC16(smb + OFF_KS(s) + sw,
                   (const char*)&g_Khi[((size_t)h * NB + b0 + r) * DKK] + c * 16);
        CP_ASYNC16(smb + OFF_KS(s) + 8192 + sw,
                   (const char*)&g_Klo[((size_t)h * NB + b0 + r) * DKK] + c * 16);
        CP_ASYNC16(smb + OFF_VS(s) + sw,
                   (const char*)&g_Vthi[((size_t)(h * DKK + r)) * NB + b0] + c * 16);
        CP_ASYNC16(smb + OFF_VS(s) + 8192 + sw,
                   (const char*)&g_Vtlo[((size_t)(h * DKK + r)) * NB + b0] + c * 16);
    }
    for (int i = tid; i < 2048; i += 256) {
        int r = i >> 4, c = i & 15;
        CP_ASYNC16(smb + OFF_WMS(s) + r * (WMP * 4) + c * 16,
                   (const char*)&g_wm[(size_t)(a0 + r) * NB + b0] + c * 16);
    }
}

// ---------------- attention mainloop (mma.sync + ldmatrix) ----------------
__global__ void __launch_bounds__(256, 1) attn_kernel() {
    extern __shared__ char sm[];
    const uint32_t smb = smem_u32(sm);
    const int tid = threadIdx.x, wid = tid >> 5, lane = tid & 31;
    const int a0 = blockIdx.x * BM, h = blockIdx.y;

    // stage Q (persistent)
    for (int i = tid; i < 1024; i += 256) {
        int r = i >> 3, c = i & 7;
        uint32_t sw = sw128(r * 128 + c * 16);
        CP_ASYNC16(smb + OFF_Q + sw,
                   (const char*)&g_Qhi[((size_t)h * NA + a0 + r) * DKK] + c * 16);
        CP_ASYNC16(smb + OFF_Q + 16384 + sw,
                   (const char*)&g_Qlo[((size_t)h * NA + a0 + r) * DKK] + c * 16);
    }
    CP_COMMIT();
    load_tiles(smb, tid, h, a0, 0); CP_COMMIT();
    load_tiles(smb, tid, h, a0, 1); CP_COMMIT();

    // Q fragments: warp owns rows wid*16 .. +15
    unsigned qh[4][4], ql[4][4];
    CP_WAITG(2);
    __syncthreads();
    {
        int qrow = wid * 16 + (lane & 15);
        int qcb = (lane >> 4) * 16;
#pragma unroll
        for (int kc = 0; kc < 4; kc++) {
            uint32_t sw = sw128(qrow * 128 + kc * 32 + qcb);
            LDSM4(qh[kc][0], qh[kc][1], qh[kc][2], qh[kc][3], smb + OFF_Q + sw);
            LDSM4(ql[kc][0], ql[kc][1], ql[kc][2], ql[kc][3], smb + OFF_Q + 16384 + sw);
        }
    }

    float oacc[8][4];
#pragma unroll
    for (int nt = 0; nt < 8; nt++)
#pragma unroll
        for (int e = 0; e < 4; e++) oacc[nt][e] = 0.f;
    float lsum0 = 0.f, lsum1 = 0.f;

    const int brow = (lane & 7) + ((lane >> 4) << 3);   // B-frag row within 16-block
    const int bkb = ((lane >> 3) & 1) * 16;             // B-frag k-byte offset
    const int er = wid * 16 + (lane >> 2);              // epilogue row (C-frag row g)

    for (int bt = 0; bt < NT; bt++) {
        const int s = bt & 1;
        CP_WAITG(1);
        __syncthreads();

        // ---- S = Q K^T (3-term bf16 split) ----
        float sacc[8][4];
#pragma unroll
        for (int nt = 0; nt < 8; nt++)
#pragma unroll
            for (int e = 0; e < 4; e++) sacc[nt][e] = 0.f;

        const uint32_t kbase = smb + OFF_KS(s);
#pragma unroll
        for (int kc = 0; kc < 4; kc++) {
            unsigned bf[4][4];
#pragma unroll
            for (int ng = 0; ng < 4; ng++) {
                uint32_t sw = sw128((ng * 16 + brow) * 128 + kc * 32 + bkb);
                LDSM4(bf[ng][0], bf[ng][1], bf[ng][2], bf[ng][3], kbase + sw);
            }
#pragma unroll
            for (int ng = 0; ng < 4; ng++) {
                mma16816(sacc[2 * ng], qh[kc], &bf[ng][0]);
                mma16816(sacc[2 * ng + 1], qh[kc], &bf[ng][2]);
                mma16816(sacc[2 * ng], ql[kc], &bf[ng][0]);
                mma16816(sacc[2 * ng + 1], ql[kc], &bf[ng][2]);
            }
#pragma unroll
            for (int ng = 0; ng < 4; ng++) {
                uint32_t sw = sw128((ng * 16 + brow) * 128 + kc * 32 + bkb);
                LDSM4(bf[ng][0], bf[ng][1], bf[ng][2], bf[ng][3], kbase + 8192 + sw);
            }
#pragma unroll
            for (int ng = 0; ng < 4; ng++) {
                mma16816(sacc[2 * ng], qh[kc], &bf[ng][0]);
                mma16816(sacc[2 * ng + 1], qh[kc], &bf[ng][2]);
            }
        }

        // ---- softmax epilogue: s=clip(s+wm); p=exp(s-10); pack P hi/lo a-frags ----
        unsigned pH[4][4], pL[4][4];
        const float* wmp0 = (const float*)(sm + OFF_WMS(s)) + er * WMP + (lane & 3) * 2;
        const float* wmp1 = wmp0 + 8 * WMP;
#pragma unroll
        for (int nt = 0; nt < 8; nt++) {
            float2 w0 = *(const float2*)(wmp0 + nt * 8);
            float2 w1 = *(const float2*)(wmp1 + nt * 8);
            float t00 = fminf(fmaxf(sacc[nt][0] + w0.x, -10.f), 10.f);
            float t01 = fminf(fmaxf(sacc[nt][1] + w0.y, -10.f), 10.f);
            float t10 = fminf(fmaxf(sacc[nt][2] + w1.x, -10.f), 10.f);
            float t11 = fminf(fmaxf(sacc[nt][3] + w1.y, -10.f), 10.f);
            float p00 = __expf(t00 - 10.f), p01 = __expf(t01 - 10.f);
            float p10 = __expf(t10 - 10.f), p11 = __expf(t11 - 10.f);
            lsum0 += p00 + p01;
            lsum1 += p10 + p11;
            unsigned h0, l0, h1, l1;
            cvt_pack(p00, p01, h0, l0);
            cvt_pack(p10, p11, h1, l1);
            int kt = nt >> 1, j = (nt & 1) * 2;
            pH[kt][j] = h0; pH[kt][j + 1] = h1;
            pL[kt][j] = l0; pL[kt][j + 1] = l1;
        }

        // ---- O += P V (3-term bf16 split) ----
        const uint32_t vbase = smb + OFF_VS(s);
#pragma unroll
        for (int kt = 0; kt < 4; kt++) {
            unsigned bf[4][4];
#pragma unroll
            for (int ng = 0; ng < 4; ng++) {
                uint32_t sw = sw128((ng * 16 + brow) * 128 + kt * 32 + bkb);
                LDSM4(bf[ng][0], bf[ng][1], bf[ng][2], bf[ng][3], vbase + sw);
            }
#pragma unroll
            for (int ng = 0; ng < 4; ng++) {
                mma16816(oacc[2 * ng], pH[kt], &bf[ng][0]);
                mma16816(oacc[2 * ng + 1], pH[kt], &bf[ng][2]);
                mma16816(oacc[2 * ng], pL[kt], &bf[ng][0]);
                mma16816(oacc[2 * ng + 1], pL[kt], &bf[ng][2]);
            }
#pragma unroll
            for (int ng = 0; ng < 4; ng++) {
                uint32_t sw = sw128((ng * 16 + brow) * 128 + kt * 32 + bkb);
                LDSM4(bf[ng][0], bf[ng][1], bf[ng][2], bf[ng][3], vbase + 8192 + sw);
            }
#pragma unroll
            for (int ng = 0; ng < 4; ng++) {
                mma16816(oacc[2 * ng], pH[kt], &bf[ng][0]);
                mma16816(oacc[2 * ng + 1], pH[kt], &bf[ng][2]);
            }
        }

        __syncthreads();
        if (bt + 2 < NT) load_tiles(smb, tid, h, a0, bt + 2);
        CP_COMMIT();
    }

    // quad-reduce row sums
    lsum0 += __shfl_xor_sync(0xFFFFFFFFu, lsum0, 1);
    lsum0 += __shfl_xor_sync(0xFFFFFFFFu, lsum0, 2);
    lsum1 += __shfl_xor_sync(0xFFFFFFFFu, lsum1, 1);
    lsum1 += __shfl_xor_sync(0xFFFFFFFFu, lsum1, 2);
    const float inv0 = 0.25f / lsum0;
    const float inv1 = 0.25f / lsum1;

    float* d0 = &g_ctx[((size_t)h * NA + a0 + er) * DKK + (lane & 3) * 2];
    float* d1 = d0 + 8 * DKK;
#pragma unroll
    for (int nt = 0; nt < 8; nt++) {
        float2 v0 = make_float2(oacc[nt][0] * inv0, oacc[nt][1] * inv0);
        float2 v1 = make_float2(oacc[nt][2] * inv1, oacc[nt][3] * inv1);
        *(float2*)(d0 + nt * 8) = v0;
        *(float2*)(d1 + nt * 8) = v1;
    }
}

// ---------------- final reduce over heads + influence ----------------
__global__ void __launch_bounds__(256) reduce_kernel(float* __restrict__ out) {
    int idx = blockIdx.x * 256 + threadIdx.x;
    const int NC = NA * DKK;
    if (idx < NC) {
        out[idx] = g_ctx[idx] + g_ctx[idx + NC] + g_ctx[idx + 2 * NC] + g_ctx[idx + 3 * NC];
    } else if (idx < NC + NA) {
        out[idx] = 1.0f;
    }
}

// ---------------- launch ----------------
extern "C" void kernel_launch(void* const* d_in, const int* in_sizes, int n_in,
                              void* d_out, int out_size)
{
    const float* a_z    = (const float*)d_in[0];
    const float* bv_z   = (const float*)d_in[1];
    const void*  mask   = d_in[2];
    const float* weight = (const float*)d_in[3];
    const float* Wq     = (const float*)d_in[4];
    const float* Wk     = (const float*)d_in[5];
    const float* Wv     = (const float*)d_in[6];
    float* out = (float*)d_out;

    detect_mask_kind<<<1, 256>>>((const unsigned int*)mask);
    prep_wm<<<8192, 256>>>((const float4*)weight, mask);
    proj_kernel<<<dim3(DD / 64, NA / 64, 3), 256>>>(a_z, bv_z, Wq, Wk, Wv);

    cudaFuncSetAttribute(attn_kernel, cudaFuncAttributeMaxDynamicSharedMemorySize, SMEM_BYTES);
    attn_kernel<<<dim3(NA / BM, HH), 256, SMEM_BYTES>>>();

    reduce_kernel<<<(NA * DKK + NA + 255) / 256, 256>>>(out);
}

// round 5
// speedup vs baseline: 4.6410x; 1.1242x over previous
#include <cuda_runtime.h>
#include <cuda_bf16.h>
#include <cstdint>

#define NA 4096
#define NB 4096
#define DD 256
#define HH 4
#define DKK 64
#define BM 128
#define BC 64
#define NT (NB / BC)
#define PMIN 2.0611536e-9f   // exp(-20)

// ---------------- device scratch ----------------
__device__ __nv_bfloat16 g_Qhi[HH * NA * DKK];
__device__ __nv_bfloat16 g_Qlo[HH * NA * DKK];
__device__ __nv_bfloat16 g_Khi[HH * NB * DKK];
__device__ __nv_bfloat16 g_Klo[HH * NB * DKK];
__device__ __nv_bfloat16 g_Vthi[HH * DKK * NB];  // [h][dk][token]
__device__ __nv_bfloat16 g_Vtlo[HH * DKK * NB];
__device__ uint8_t g_mask8[(size_t)NA * NB];
__device__ float g_ctx[HH * NA * DKK];
__device__ int g_mask_kind;

// ---------------- helpers ----------------
__device__ __forceinline__ uint32_t smem_u32(const void* p) {
    uint32_t a;
    asm("{ .reg .u64 t; cvta.to.shared.u64 t, %1; cvt.u32.u64 %0, t; }" : "=r"(a) : "l"(p));
    return a;
}
__device__ __forceinline__ uint32_t sw128(uint32_t o) { return o ^ ((o >> 3) & 0x70); }

#define CP_ASYNC16(dst, src) \
    asm volatile("cp.async.cg.shared.global [%0], [%1], 16;\n" :: "r"(dst), "l"(src))
#define CP_COMMIT()  asm volatile("cp.async.commit_group;\n" ::: "memory")
#define CP_WAITG(n)  asm volatile("cp.async.wait_group %0;\n" :: "n"(n) : "memory")

#define LDSM4(r0, r1, r2, r3, a) \
    asm volatile("ldmatrix.sync.aligned.m8n8.x4.shared.b16 {%0,%1,%2,%3}, [%4];" \
                 : "=r"(r0), "=r"(r1), "=r"(r2), "=r"(r3) : "r"(a))

__device__ __forceinline__ void mma16816(float* c, const unsigned* a, const unsigned* b) {
    asm volatile(
        "mma.sync.aligned.m16n8k16.row.col.f32.bf16.bf16.f32 "
        "{%0,%1,%2,%3}, {%4,%5,%6,%7}, {%8,%9}, {%0,%1,%2,%3};\n"
        : "+f"(c[0]), "+f"(c[1]), "+f"(c[2]), "+f"(c[3])
        : "r"(a[0]), "r"(a[1]), "r"(a[2]), "r"(a[3]), "r"(b[0]), "r"(b[1]));
}

__device__ __forceinline__ void cvt_pack(float x0, float x1, unsigned& hi, unsigned& lo) {
    __nv_bfloat16 h0 = __float2bfloat16(x0), h1 = __float2bfloat16(x1);
    __nv_bfloat16 l0 = __float2bfloat16(x0 - __bfloat162float(h0));
    __nv_bfloat16 l1 = __float2bfloat16(x1 - __bfloat162float(h1));
    hi = ((unsigned)__bfloat16_as_ushort(h1) << 16) | (unsigned)__bfloat16_as_ushort(h0);
    lo = ((unsigned)__bfloat16_as_ushort(l1) << 16) | (unsigned)__bfloat16_as_ushort(l0);
}

__device__ __forceinline__ float san(float x) {
    if (isnan(x)) return 0.f;
    if (isinf(x)) return x > 0.f ? 1.f : -1.f;
    return x;
}

// ---------------- mask dtype detector ----------------
__global__ void detect_mask_kind(const unsigned int* __restrict__ m) {
    __shared__ int s_i32, s_f32;
    if (threadIdx.x == 0) { s_i32 = 1; s_f32 = 1; }
    __syncthreads();
    int ok_i = 1, ok_f = 1;
    for (int i = threadIdx.x; i < 4096; i += 1024) {
        unsigned v = m[i];
        ok_i &= (v <= 1u);
        ok_f &= (v == 0u || v == 0x3F800000u);
    }
    if (!ok_i) atomicAnd(&s_i32, 0);
    if (!ok_f) atomicAnd(&s_f32, 0);
    __syncthreads();
    if (threadIdx.x == 0) g_mask_kind = s_i32 ? 1 : (s_f32 ? 2 : 0);
}

// ---------------- mask normalize to u8 ----------------
__global__ void __launch_bounds__(256) normalize_mask(const void* __restrict__ mraw) {
    const int kind = g_mask_kind;
    const size_t n4 = (size_t)NA * NB / 4;
    size_t i = (size_t)blockIdx.x * 256 + threadIdx.x;
    const size_t stride = (size_t)gridDim.x * 256;
    for (; i < n4; i += stride) {
        uchar4 o;
        if (kind == 1) {
            int4 m = ((const int4*)mraw)[i];
            o = make_uchar4(m.x != 0, m.y != 0, m.z != 0, m.w != 0);
        } else if (kind == 2) {
            float4 m = ((const float4*)mraw)[i];
            o = make_uchar4(m.x != 0.f, m.y != 0.f, m.z != 0.f, m.w != 0.f);
        } else {
            uchar4 m = ((const uchar4*)mraw)[i];
            o = make_uchar4(m.x != 0, m.y != 0, m.z != 0, m.w != 0);
        }
        ((uchar4*)g_mask8)[i] = o;
    }
}

// ---------------- projections via mma.sync (3-term bf16 split) ----------------
// out = X @ W^T ; grid (NA/128, 2, 3); CTA: 128 rows x 128 cols, K=256 in 4 chunks of 64
#define PJ_XF(s)  ((s) * 32768)
#define PJ_WF(s)  (65536 + (s) * 32768)
#define PJ_XHI 131072
#define PJ_XLO 147456
#define PJ_WHI 163840
#define PJ_WLO 180224
#define PJ_SMEM 196608

__global__ void __launch_bounds__(256, 1) proj_mma(
    const float* __restrict__ a_z, const float* __restrict__ bv_z,
    const float* __restrict__ Wq, const float* __restrict__ Wk, const float* __restrict__ Wv)
{
    extern __shared__ char sm[];
    const uint32_t smb = smem_u32(sm);
    const int tid = threadIdx.x, wid = tid >> 5, lane = tid & 31;
    const int mat = blockIdx.z;
    const int m0 = blockIdx.x * 128, nb = blockIdx.y * 128;
    const float* X = (mat == 0) ? a_z : bv_z;
    const float* W = (mat == 0) ? Wq : (mat == 1 ? Wk : Wv);

    // stage chunk c (fp32) via cp.async
    auto load_chunk = [&](int c) {
        const int s = c & 1;
        for (int i = tid; i < 2048; i += 256) {
            int r = i >> 4, q = i & 15;
            CP_ASYNC16(smb + PJ_XF(s) + r * 256 + q * 16,
                       (const char*)&X[(size_t)(m0 + r) * DD + c * 64] + q * 16);
            CP_ASYNC16(smb + PJ_WF(s) + r * 256 + q * 16,
                       (const char*)&W[(size_t)(nb + r) * DD + c * 64] + q * 16);
        }
    };
    load_chunk(0); CP_COMMIT();
    load_chunk(1); CP_COMMIT();

    float oacc[16][4];
#pragma unroll
    for (int nt = 0; nt < 16; nt++)
#pragma unroll
        for (int e = 0; e < 4; e++) oacc[nt][e] = 0.f;

    const int arow = wid * 16 + (lane & 15);
    const int akb = (lane >> 4) * 16;
    const int brow = (lane & 7) + ((lane >> 4) << 3);
    const int bkb = ((lane >> 3) & 1) * 16;

    for (int c = 0; c < 4; c++) {
        const int s = c & 1;
        CP_WAITG(1);
        __syncthreads();
        // convert fp32 -> bf16 hi/lo (X sanitized)
#pragma unroll
        for (int j = 0; j < 16; j++) {
            int p = tid + j * 256;
            int r = p >> 5, cp2 = p & 31;
            float2 xv = *(const float2*)(sm + PJ_XF(s) + r * 256 + cp2 * 8);
            float2 wv = *(const float2*)(sm + PJ_WF(s) + r * 256 + cp2 * 8);
            unsigned hi, lo;
            cvt_pack(san(xv.x), san(xv.y), hi, lo);
            uint32_t off = sw128(r * 128 + cp2 * 4);
            *(uint32_t*)(sm + PJ_XHI + off) = hi;
            *(uint32_t*)(sm + PJ_XLO + off) = lo;
            cvt_pack(wv.x, wv.y, hi, lo);
            *(uint32_t*)(sm + PJ_WHI + off) = hi;
            *(uint32_t*)(sm + PJ_WLO + off) = lo;
        }
        __syncthreads();
        // MMA over this chunk
#pragma unroll
        for (int kc = 0; kc < 4; kc++) {
            unsigned ah[4], al[4];
            uint32_t asw = sw128(arow * 128 + kc * 32 + akb);
            LDSM4(ah[0], ah[1], ah[2], ah[3], smb + PJ_XHI + asw);
            LDSM4(al[0], al[1], al[2], al[3], smb + PJ_XLO + asw);
#pragma unroll
            for (int ng = 0; ng < 8; ng++) {
                unsigned bh[4], bl[4];
                uint32_t bsw = sw128((ng * 16 + brow) * 128 + kc * 32 + bkb);
                LDSM4(bh[0], bh[1], bh[2], bh[3], smb + PJ_WHI + bsw);
                LDSM4(bl[0], bl[1], bl[2], bl[3], smb + PJ_WLO + bsw);
                mma16816(oacc[2 * ng], ah, &bh[0]);
                mma16816(oacc[2 * ng + 1], ah, &bh[2]);
                mma16816(oacc[2 * ng], al, &bh[0]);
                mma16816(oacc[2 * ng + 1], al, &bh[2]);
                mma16816(oacc[2 * ng], ah, &bl[0]);
                mma16816(oacc[2 * ng + 1], ah, &bl[2]);
            }
        }
        __syncthreads();
        if (c + 2 < 4) load_chunk(c + 2);
        CP_COMMIT();
    }

    // writeback (split to bf16 hi/lo, per-head layouts)
    const float scale = (mat == 0) ? 0.125f : 1.0f;
    const int er = wid * 16 + (lane >> 2);
    const int tcol = (lane & 3) * 2;
#pragma unroll
    for (int nt = 0; nt < 16; nt++) {
#pragma unroll
        for (int hf = 0; hf < 2; hf++) {
            int row = m0 + er + hf * 8;
            int col = nb + nt * 8 + tcol;
            int head = col >> 6, cc = col & 63;
            float x0 = oacc[nt][2 * hf] * scale;
            float x1 = oacc[nt][2 * hf + 1] * scale;
            if (mat == 2) {
                __nv_bfloat16 h0 = __float2bfloat16(x0);
                __nv_bfloat16 l0 = __float2bfloat16(x0 - __bfloat162float(h0));
                __nv_bfloat16 h1 = __float2bfloat16(x1);
                __nv_bfloat16 l1 = __float2bfloat16(x1 - __bfloat162float(h1));
                size_t o0 = (size_t)(head * DKK + cc) * NB + row;
                size_t o1 = (size_t)(head * DKK + cc + 1) * NB + row;
                g_Vthi[o0] = h0; g_Vtlo[o0] = l0;
                g_Vthi[o1] = h1; g_Vtlo[o1] = l1;
            } else {
                unsigned hi, lo;
                cvt_pack(x0, x1, hi, lo);
                size_t o = (size_t)(head * NA + row) * DKK + cc;
                if (mat == 0) {
                    *(unsigned*)&g_Qhi[o] = hi; *(unsigned*)&g_Qlo[o] = lo;
                } else {
                    *(unsigned*)&g_Khi[o] = hi; *(unsigned*)&g_Klo[o] = lo;
                }
            }
        }
    }
}

// ---------------- attention smem layout ----------------
#define WMP 76                                   // weight row pitch in floats (304B)
#define MPITCH 80
#define OFF_Q 0
#define OFF_KS(s)  (32768 + (s) * 16384)
#define OFF_VS(s)  (65536 + (s) * 16384)
#define OFF_WMS(s) (98304 + (s) * 38912)
#define OFF_MS(s)  (176128 + (s) * 10240)
#define SMEM_BYTES 196608

__device__ __forceinline__ void load_tiles(uint32_t smb, int tid, int h, int a0, int bt,
                                           const float* __restrict__ weight) {
    const int s = bt & 1, b0 = bt * BC;
    for (int i = tid; i < 512; i += 256) {
        int r = i >> 3, c = i & 7;
        uint32_t sw = sw128(r * 128 + c * 16);
        CP_ASYNC16(smb + OFF_KS(s) + sw,
                   (const char*)&g_Khi[((size_t)h * NB + b0 + r) * DKK] + c * 16);
        CP_ASYNC16(smb + OFF_KS(s) + 8192 + sw,
                   (const char*)&g_Klo[((size_t)h * NB + b0 + r) * DKK] + c * 16);
        CP_ASYNC16(smb + OFF_VS(s) + sw,
                   (const char*)&g_Vthi[((size_t)(h * DKK + r)) * NB + b0] + c * 16);
        CP_ASYNC16(smb + OFF_VS(s) + 8192 + sw,
                   (const char*)&g_Vtlo[((size_t)(h * DKK + r)) * NB + b0] + c * 16);
    }
    for (int i = tid; i < 2048; i += 256) {
        int r = i >> 4, c = i & 15;
        CP_ASYNC16(smb + OFF_WMS(s) + r * (WMP * 4) + c * 16,
                   (const char*)&weight[(size_t)(a0 + r) * NB + b0] + c * 16);
    }
    for (int i = tid; i < 512; i += 256) {
        int r = i >> 2, c = i & 3;
        CP_ASYNC16(smb + OFF_MS(s) + r * MPITCH + c * 16,
                   (const char*)&g_mask8[(size_t)(a0 + r) * NB + b0] + c * 16);
    }
}

// ---------------- attention mainloop ----------------
__global__ void __launch_bounds__(256, 1) attn_kernel(const float* __restrict__ weight) {
    extern __shared__ char sm[];
    const uint32_t smb = smem_u32(sm);
    const int tid = threadIdx.x, wid = tid >> 5, lane = tid & 31;
    const int a0 = blockIdx.x * BM, h = blockIdx.y;

    for (int i = tid; i < 1024; i += 256) {
        int r = i >> 3, c = i & 7;
        uint32_t sw = sw128(r * 128 + c * 16);
        CP_ASYNC16(smb + OFF_Q + sw,
                   (const char*)&g_Qhi[((size_t)h * NA + a0 + r) * DKK] + c * 16);
        CP_ASYNC16(smb + OFF_Q + 16384 + sw,
                   (const char*)&g_Qlo[((size_t)h * NA + a0 + r) * DKK] + c * 16);
    }
    CP_COMMIT();
    load_tiles(smb, tid, h, a0, 0, weight); CP_COMMIT();
    load_tiles(smb, tid, h, a0, 1, weight); CP_COMMIT();

    unsigned qh[4][4], ql[4][4];
    CP_WAITG(2);
    __syncthreads();
    {
        int qrow = wid * 16 + (lane & 15);
        int qcb = (lane >> 4) * 16;
#pragma unroll
        for (int kc = 0; kc < 4; kc++) {
            uint32_t sw = sw128(qrow * 128 + kc * 32 + qcb);
            LDSM4(qh[kc][0], qh[kc][1], qh[kc][2], qh[kc][3], smb + OFF_Q + sw);
            LDSM4(ql[kc][0], ql[kc][1], ql[kc][2], ql[kc][3], smb + OFF_Q + 16384 + sw);
        }
    }

    float oacc[8][4];
#pragma unroll
    for (int nt = 0; nt < 8; nt++)
#pragma unroll
        for (int e = 0; e < 4; e++) oacc[nt][e] = 0.f;
    float lsum0 = 0.f, lsum1 = 0.f;

    const int brow = (lane & 7) + ((lane >> 4) << 3);
    const int bkb = ((lane >> 3) & 1) * 16;
    const int er = wid * 16 + (lane >> 2);
    const int tcol = (lane & 3) * 2;

    for (int bt = 0; bt < NT; bt++) {
        const int s = bt & 1;
        CP_WAITG(1);
        __syncthreads();

        // ---- S = Q K^T ----
        float sacc[8][4];
#pragma unroll
        for (int nt = 0; nt < 8; nt++)
#pragma unroll
            for (int e = 0; e < 4; e++) sacc[nt][e] = 0.f;

        const uint32_t kbase = smb + OFF_KS(s);
#pragma unroll
        for (int kc = 0; kc < 4; kc++) {
            unsigned bh[4][4], bl[4][4];
#pragma unroll
            for (int ng = 0; ng < 4; ng++) {
                uint32_t sw = sw128((ng * 16 + brow) * 128 + kc * 32 + bkb);
                LDSM4(bh[ng][0], bh[ng][1], bh[ng][2], bh[ng][3], kbase + sw);
                LDSM4(bl[ng][0], bl[ng][1], bl[ng][2], bl[ng][3], kbase + 8192 + sw);
            }
#pragma unroll
            for (int ng = 0; ng < 4; ng++) {
                mma16816(sacc[2 * ng], qh[kc], &bh[ng][0]);
                mma16816(sacc[2 * ng + 1], qh[kc], &bh[ng][2]);
                mma16816(sacc[2 * ng], ql[kc], &bh[ng][0]);
                mma16816(sacc[2 * ng + 1], ql[kc], &bh[ng][2]);
                mma16816(sacc[2 * ng], qh[kc], &bl[ng][0]);
                mma16816(sacc[2 * ng + 1], qh[kc], &bl[ng][2]);
            }
        }

        // ---- softmax epilogue ----
        unsigned pH[4][4], pL[4][4];
        const float* wp0 = (const float*)(sm + OFF_WMS(s)) + er * WMP + tcol;
        const float* wp1 = wp0 + 8 * WMP;
        const uint8_t* mr0 = (const uint8_t*)(sm + OFF_MS(s)) + er * MPITCH + tcol;
        const uint8_t* mr1 = mr0 + 8 * MPITCH;
#pragma unroll
        for (int nt = 0; nt < 8; nt++) {
            float2 w0 = *(const float2*)(wp0 + nt * 8);
            float2 w1 = *(const float2*)(wp1 + nt * 8);
            unsigned short m0 = *(const unsigned short*)(mr0 + nt * 8);
            unsigned short m1 = *(const unsigned short*)(mr1 + nt * 8);
            float t00 = fminf(fmaxf(sacc[nt][0] + w0.x, -10.f), 10.f);
            float t01 = fminf(fmaxf(sacc[nt][1] + w0.y, -10.f), 10.f);
            float t10 = fminf(fmaxf(sacc[nt][2] + w1.x, -10.f), 10.f);
            float t11 = fminf(fmaxf(sacc[nt][3] + w1.y, -10.f), 10.f);
            float p00 = (m0 & 0xFF)  ? __expf(t00 - 10.f) : PMIN;
            float p01 = (m0 >> 8)    ? __expf(t01 - 10.f) : PMIN;
            float p10 = (m1 & 0xFF)  ? __expf(t10 - 10.f) : PMIN;
            float p11 = (m1 >> 8)    ? __expf(t11 - 10.f) : PMIN;
            lsum0 += p00 + p01;
            lsum1 += p10 + p11;
            unsigned h0, l0, h1, l1;
            cvt_pack(p00, p01, h0, l0);
            cvt_pack(p10, p11, h1, l1);
            int kt = nt >> 1, j = (nt & 1) * 2;
            pH[kt][j] = h0; pH[kt][j + 1] = h1;
            pL[kt][j] = l0; pL[kt][j + 1] = l1;
        }

        // ---- O += P V ----
        const uint32_t vbase = smb + OFF_VS(s);
#pragma unroll
        for (int kt = 0; kt < 4; kt++) {
            unsigned bh[4][4], bl[4][4];
#pragma unroll
            for (int ng = 0; ng < 4; ng++) {
                uint32_t sw = sw128((ng * 16 + brow) * 128 + kt * 32 + bkb);
                LDSM4(bh[ng][0], bh[ng][1], bh[ng][2], bh[ng][3], vbase + sw);
                LDSM4(bl[ng][0], bl[ng][1], bl[ng][2], bl[ng][3], vbase + 8192 + sw);
            }
#pragma unroll
            for (int ng = 0; ng < 4; ng++) {
                mma16816(oacc[2 * ng], pH[kt], &bh[ng][0]);
                mma16816(oacc[2 * ng + 1], pH[kt], &bh[ng][2]);
                mma16816(oacc[2 * ng], pL[kt], &bh[ng][0]);
                mma16816(oacc[2 * ng + 1], pL[kt], &bh[ng][2]);
                mma16816(oacc[2 * ng], pH[kt], &bl[ng][0]);
                mma16816(oacc[2 * ng + 1], pH[kt], &bl[ng][2]);
            }
        }

        __syncthreads();
        if (bt + 2 < NT) load_tiles(smb, tid, h, a0, bt + 2, weight);
        CP_COMMIT();
    }

    lsum0 += __shfl_xor_sync(0xFFFFFFFFu, lsum0, 1);
    lsum0 += __shfl_xor_sync(0xFFFFFFFFu, lsum0, 2);
    lsum1 += __shfl_xor_sync(0xFFFFFFFFu, lsum1, 1);
    lsum1 += __shfl_xor_sync(0xFFFFFFFFu, lsum1, 2);
    const float inv0 = 0.25f / lsum0;
    const float inv1 = 0.25f / lsum1;

    float* d0 = &g_ctx[((size_t)h * NA + a0 + er) * DKK + tcol];
    float* d1 = d0 + 8 * DKK;
#pragma unroll
    for (int nt = 0; nt < 8; nt++) {
        *(float2*)(d0 + nt * 8) = make_float2(oacc[nt][0] * inv0, oacc[nt][1] * inv0);
        *(float2*)(d1 + nt * 8) = make_float2(oacc[nt][2] * inv1, oacc[nt][3] * inv1);
    }
}

// ---------------- final reduce ----------------
__global__ void __launch_bounds__(256) reduce_kernel(float* __restrict__ out) {
    int idx = blockIdx.x * 256 + threadIdx.x;
    const int NC = NA * DKK;
    if (idx < NC) {
        out[idx] = g_ctx[idx] + g_ctx[idx + NC] + g_ctx[idx + 2 * NC] + g_ctx[idx + 3 * NC];
    } else if (idx < NC + NA) {
        out[idx] = 1.0f;
    }
}

// ---------------- launch ----------------
extern "C" void kernel_launch(void* const* d_in, const int* in_sizes, int n_in,
                              void* d_out, int out_size)
{
    const float* a_z    = (const float*)d_in[0];
    const float* bv_z   = (const float*)d_in[1];
    const void*  mask   = d_in[2];
    const float* weight = (const float*)d_in[3];
    const float* Wq     = (const float*)d_in[4];
    const float* Wk     = (const float*)d_in[5];
    const float* Wv     = (const float*)d_in[6];
    float* out = (float*)d_out;

    detect_mask_kind<<<1, 1024>>>((const unsigned int*)mask);
    normalize_mask<<<4096, 256>>>(mask);

    cudaFuncSetAttribute(proj_mma, cudaFuncAttributeMaxDynamicSharedMemorySize, PJ_SMEM);
    proj_mma<<<dim3(NA / 128, 2, 3), 256, PJ_SMEM>>>(a_z, bv_z, Wq, Wk, Wv);

    cudaFuncSetAttribute(attn_kernel, cudaFuncAttributeMaxDynamicSharedMemorySize, SMEM_BYTES);
    attn_kernel<<<dim3(NA / BM, HH), 256, SMEM_BYTES>>>(weight);

    reduce_kernel<<<(NA * DKK + NA + 255) / 256, 256>>>(out);
}

// round 6
// speedup vs baseline: 4.9414x; 1.0647x over previous
#include <cuda_runtime.h>
#include <cuda_bf16.h>
#include <cstdint>

#define NA 4096
#define NB 4096
#define DD 256
#define HH 4
#define DKK 64
#define BM 128
#define BC 64
#define NT (NB / BC)

// ---------------- device scratch ----------------
__device__ __nv_bfloat16 g_Qhi[HH * NA * DKK];
__device__ __nv_bfloat16 g_Qlo[HH * NA * DKK];
__device__ __nv_bfloat16 g_Khi[HH * NB * DKK];
__device__ __nv_bfloat16 g_Klo[HH * NB * DKK];
__device__ __nv_bfloat16 g_Vthi[HH * DKK * NB];  // [h][dk][token]
__device__ __nv_bfloat16 g_Vtlo[HH * DKK * NB];
__device__ float g_wm[(size_t)NA * NB];          // san(weight) + (mask?0:-1e4)
__device__ float g_ctx[HH * NA * DKK];
__device__ int g_mask_kind;

// ---------------- helpers ----------------
__device__ __forceinline__ uint32_t smem_u32(const void* p) {
    uint32_t a;
    asm("{ .reg .u64 t; cvta.to.shared.u64 t, %1; cvt.u32.u64 %0, t; }" : "=r"(a) : "l"(p));
    return a;
}
__device__ __forceinline__ uint32_t sw128(uint32_t o) { return o ^ ((o >> 3) & 0x70); }

#define CP_ASYNC16(dst, src) \
    asm volatile("cp.async.cg.shared.global [%0], [%1], 16;\n" :: "r"(dst), "l"(src))
#define CP_COMMIT()  asm volatile("cp.async.commit_group;\n" ::: "memory")
#define CP_WAITG(n)  asm volatile("cp.async.wait_group %0;\n" :: "n"(n) : "memory")

#define LDSM4(r0, r1, r2, r3, a) \
    asm volatile("ldmatrix.sync.aligned.m8n8.x4.shared.b16 {%0,%1,%2,%3}, [%4];" \
                 : "=r"(r0), "=r"(r1), "=r"(r2), "=r"(r3) : "r"(a))

__device__ __forceinline__ void mma16816(float* c, const unsigned* a, const unsigned* b) {
    asm volatile(
        "mma.sync.aligned.m16n8k16.row.col.f32.bf16.bf16.f32 "
        "{%0,%1,%2,%3}, {%4,%5,%6,%7}, {%8,%9}, {%0,%1,%2,%3};\n"
        : "+f"(c[0]), "+f"(c[1]), "+f"(c[2]), "+f"(c[3])
        : "r"(a[0]), "r"(a[1]), "r"(a[2]), "r"(a[3]), "r"(b[0]), "r"(b[1]));
}

__device__ __forceinline__ void cvt_pack(float x0, float x1, unsigned& hi, unsigned& lo) {
    __nv_bfloat16 h0 = __float2bfloat16(x0), h1 = __float2bfloat16(x1);
    __nv_bfloat16 l0 = __float2bfloat16(x0 - __bfloat162float(h0));
    __nv_bfloat16 l1 = __float2bfloat16(x1 - __bfloat162float(h1));
    hi = ((unsigned)__bfloat16_as_ushort(h1) << 16) | (unsigned)__bfloat16_as_ushort(h0);
    lo = ((unsigned)__bfloat16_as_ushort(l1) << 16) | (unsigned)__bfloat16_as_ushort(l0);
}

__device__ __forceinline__ float san(float x) {
    if (isnan(x)) return 0.f;
    if (isinf(x)) return x > 0.f ? 1.f : -1.f;
    return x;
}

// ---------------- mask dtype detector ----------------
__global__ void detect_mask_kind(const unsigned int* __restrict__ m) {
    __shared__ int s_i32, s_f32;
    if (threadIdx.x == 0) { s_i32 = 1; s_f32 = 1; }
    __syncthreads();
    int ok_i = 1, ok_f = 1;
    for (int i = threadIdx.x; i < 4096; i += 1024) {
        unsigned v = m[i];
        ok_i &= (v <= 1u);
        ok_f &= (v == 0u || v == 0x3F800000u);
    }
    if (!ok_i) atomicAnd(&s_i32, 0);
    if (!ok_f) atomicAnd(&s_f32, 0);
    __syncthreads();
    if (threadIdx.x == 0) g_mask_kind = s_i32 ? 1 : (s_f32 ? 2 : 0);
}

// ---------------- prep: fold sanitize + mask into weight ----------------
__global__ void __launch_bounds__(256) prep_wm(const float4* __restrict__ w4,
                                               const void* __restrict__ mraw) {
    const int kind = g_mask_kind;
    const size_t n4 = (size_t)NA * NB / 4;
    size_t i = (size_t)blockIdx.x * 256 + threadIdx.x;
    const size_t stride = (size_t)gridDim.x * 256;
    for (; i < n4; i += stride) {
        float4 w = w4[i];
        w.x = san(w.x); w.y = san(w.y); w.z = san(w.z); w.w = san(w.w);
        int b0, b1, b2, b3;
        if (kind == 1) {
            int4 m = ((const int4*)mraw)[i];
            b0 = m.x != 0; b1 = m.y != 0; b2 = m.z != 0; b3 = m.w != 0;
        } else if (kind == 2) {
            float4 m = ((const float4*)mraw)[i];
            b0 = m.x != 0.f; b1 = m.y != 0.f; b2 = m.z != 0.f; b3 = m.w != 0.f;
        } else {
            uchar4 m = ((const uchar4*)mraw)[i];
            b0 = m.x != 0; b1 = m.y != 0; b2 = m.z != 0; b3 = m.w != 0;
        }
        float4 o;
        o.x = w.x + (b0 ? 0.f : -10000.f);
        o.y = w.y + (b1 ? 0.f : -10000.f);
        o.z = w.z + (b2 ? 0.f : -10000.f);
        o.w = w.w + (b3 ? 0.f : -10000.f);
        ((float4*)g_wm)[i] = o;
    }
}

// ---------------- projections via mma.sync (3-term bf16 split) ----------------
#define PJ_XF(s)  ((s) * 32768)
#define PJ_WF(s)  (65536 + (s) * 32768)
#define PJ_XHI 131072
#define PJ_XLO 147456
#define PJ_WHI 163840
#define PJ_WLO 180224
#define PJ_SMEM 196608
#define VT_PITCH 132

__global__ void __launch_bounds__(256, 1) proj_mma(
    const float* __restrict__ a_z, const float* __restrict__ bv_z,
    const float* __restrict__ Wq, const float* __restrict__ Wk, const float* __restrict__ Wv)
{
    extern __shared__ char sm[];
    const uint32_t smb = smem_u32(sm);
    const int tid = threadIdx.x, wid = tid >> 5, lane = tid & 31;
    const int mat = blockIdx.z;
    const int m0 = blockIdx.x * 128, nb = blockIdx.y * 128;
    const float* X = (mat == 0) ? a_z : bv_z;
    const float* W = (mat == 0) ? Wq : (mat == 1 ? Wk : Wv);

    auto load_chunk = [&](int c) {
        const int s = c & 1;
        for (int i = tid; i < 2048; i += 256) {
            int r = i >> 4, q = i & 15;
            CP_ASYNC16(smb + PJ_XF(s) + r * 256 + q * 16,
                       (const char*)&X[(size_t)(m0 + r) * DD + c * 64] + q * 16);
            CP_ASYNC16(smb + PJ_WF(s) + r * 256 + q * 16,
                       (const char*)&W[(size_t)(nb + r) * DD + c * 64] + q * 16);
        }
    };
    load_chunk(0); CP_COMMIT();
    load_chunk(1); CP_COMMIT();

    float oacc[16][4];
#pragma unroll
    for (int nt = 0; nt < 16; nt++)
#pragma unroll
        for (int e = 0; e < 4; e++) oacc[nt][e] = 0.f;

    const int arow = wid * 16 + (lane & 15);
    const int akb = (lane >> 4) * 16;
    const int brow = (lane & 7) + ((lane >> 4) << 3);
    const int bkb = ((lane >> 3) & 1) * 16;

    for (int c = 0; c < 4; c++) {
        const int s = c & 1;
        CP_WAITG(1);
        __syncthreads();
#pragma unroll
        for (int j = 0; j < 16; j++) {
            int p = tid + j * 256;
            int r = p >> 5, cp2 = p & 31;
            float2 xv = *(const float2*)(sm + PJ_XF(s) + r * 256 + cp2 * 8);
            float2 wv = *(const float2*)(sm + PJ_WF(s) + r * 256 + cp2 * 8);
            unsigned hi, lo;
            cvt_pack(san(xv.x), san(xv.y), hi, lo);
            uint32_t off = sw128(r * 128 + cp2 * 4);
            *(uint32_t*)(sm + PJ_XHI + off) = hi;
            *(uint32_t*)(sm + PJ_XLO + off) = lo;
            cvt_pack(wv.x, wv.y, hi, lo);
            *(uint32_t*)(sm + PJ_WHI + off) = hi;
            *(uint32_t*)(sm + PJ_WLO + off) = lo;
        }
        __syncthreads();
#pragma unroll
        for (int kc = 0; kc < 4; kc++) {
            unsigned ah[4], al[4];
            uint32_t asw = sw128(arow * 128 + kc * 32 + akb);
            LDSM4(ah[0], ah[1], ah[2], ah[3], smb + PJ_XHI + asw);
            LDSM4(al[0], al[1], al[2], al[3], smb + PJ_XLO + asw);
#pragma unroll
            for (int ng = 0; ng < 8; ng++) {
                unsigned bh[4], bl[4];
                uint32_t bsw = sw128((ng * 16 + brow) * 128 + kc * 32 + bkb);
                LDSM4(bh[0], bh[1], bh[2], bh[3], smb + PJ_WHI + bsw);
                LDSM4(bl[0], bl[1], bl[2], bl[3], smb + PJ_WLO + bsw);
                mma16816(oacc[2 * ng], ah, &bh[0]);
                mma16816(oacc[2 * ng + 1], ah, &bh[2]);
                mma16816(oacc[2 * ng], al, &bh[0]);
                mma16816(oacc[2 * ng + 1], al, &bh[2]);
                mma16816(oacc[2 * ng], ah, &bl[0]);
                mma16816(oacc[2 * ng + 1], ah, &bl[2]);
            }
        }
        __syncthreads();
        if (c + 2 < 4) load_chunk(c + 2);
        CP_COMMIT();
    }

    const int er = wid * 16 + (lane >> 2);
    const int tcol = (lane & 3) * 2;

    if (mat == 2) {
        // transpose V tile through smem, then vectorized stores to g_Vt
        float* smf = (float*)sm;
#pragma unroll
        for (int nt = 0; nt < 16; nt++)
#pragma unroll
            for (int hf = 0; hf < 2; hf++) {
                int row = er + hf * 8;
                int col = nt * 8 + tcol;
                smf[(col) * VT_PITCH + row] = oacc[nt][2 * hf];
                smf[(col + 1) * VT_PITCH + row] = oacc[nt][2 * hf + 1];
            }
        __syncthreads();
        for (int idx = tid; idx < 128 * 32; idx += 256) {
            int c = idx >> 5, tb = idx & 31;      // col local, token block of 4
            const float* src = &smf[c * VT_PITCH + tb * 4];
            float x0 = src[0], x1 = src[1], x2 = src[2], x3 = src[3];
            unsigned h0, l0, h1, l1;
            cvt_pack(x0, x1, h0, l0);
            cvt_pack(x2, x3, h1, l1);
            int col = nb + c;
            int head = col >> 6, cc = col & 63;
            size_t o = (size_t)(head * DKK + cc) * NB + m0 + tb * 4;
            *(uint2*)&g_Vthi[o] = make_uint2(h0, h1);
            *(uint2*)&g_Vtlo[o] = make_uint2(l0, l1);
        }
    } else {
        const float scale = (mat == 0) ? 0.125f : 1.0f;
#pragma unroll
        for (int nt = 0; nt < 16; nt++) {
#pragma unroll
            for (int hf = 0; hf < 2; hf++) {
                int row = m0 + er + hf * 8;
                int col = nb + nt * 8 + tcol;
                int head = col >> 6, cc = col & 63;
                float x0 = oacc[nt][2 * hf] * scale;
                float x1 = oacc[nt][2 * hf + 1] * scale;
                unsigned hi, lo;
                cvt_pack(x0, x1, hi, lo);
                size_t o = (size_t)(head * NA + row) * DKK + cc;
                if (mat == 0) {
                    *(unsigned*)&g_Qhi[o] = hi; *(unsigned*)&g_Qlo[o] = lo;
                } else {
                    *(unsigned*)&g_Khi[o] = hi; *(unsigned*)&g_Klo[o] = lo;
                }
            }
        }
    }
}

// ---------------- attention smem layout ----------------
#define WMP 76
#define OFF_Q 0
#define OFF_KS(s)  (32768 + (s) * 16384)
#define OFF_VS(s)  (65536 + (s) * 16384)
#define OFF_WMS(s) (98304 + (s) * 38912)
#define OFF_OC 32768      // O-combine buffer (reuses K stages after mainloop)
#define OFF_LS 0          // lsum combine (reuses Q region after mainloop)
#define SMEM_BYTES 176128

__device__ __forceinline__ void load_tiles(uint32_t smb, int tid, int h, int a0, int bt) {
    const int s = bt & 1, b0 = bt * BC;
    for (int i = tid; i < 512; i += 512) {
        int r = i >> 3, c = i & 7;
        uint32_t sw = sw128(r * 128 + c * 16);
        CP_ASYNC16(smb + OFF_KS(s) + sw,
                   (const char*)&g_Khi[((size_t)h * NB + b0 + r) * DKK] + c * 16);
        CP_ASYNC16(smb + OFF_KS(s) + 8192 + sw,
                   (const char*)&g_Klo[((size_t)h * NB + b0 + r) * DKK] + c * 16);
        CP_ASYNC16(smb + OFF_VS(s) + sw,
                   (const char*)&g_Vthi[((size_t)(h * DKK + r)) * NB + b0] + c * 16);
        CP_ASYNC16(smb + OFF_VS(s) + 8192 + sw,
                   (const char*)&g_Vtlo[((size_t)(h * DKK + r)) * NB + b0] + c * 16);
    }
    for (int i = tid; i < 2048; i += 512) {
        int r = i >> 4, c = i & 15;
        CP_ASYNC16(smb + OFF_WMS(s) + r * (WMP * 4) + c * 16,
                   (const char*)&g_wm[(size_t)(a0 + r) * NB + b0] + c * 16);
    }
}

// ---------------- attention mainloop: 512 threads, BC split across 2 warpgroups ----------------
__global__ void __launch_bounds__(512, 1) attn_kernel() {
    extern __shared__ char sm[];
    const uint32_t smb = smem_u32(sm);
    const int tid = threadIdx.x, wid = tid >> 5, lane = tid & 31;
    const int wg = wid >> 3, wrow = wid & 7;
    const int a0 = blockIdx.x * BM, h = blockIdx.y;

    for (int i = tid; i < 1024; i += 512) {
        int r = i >> 3, c = i & 7;
        uint32_t sw = sw128(r * 128 + c * 16);
        CP_ASYNC16(smb + OFF_Q + sw,
                   (const char*)&g_Qhi[((size_t)h * NA + a0 + r) * DKK] + c * 16);
        CP_ASYNC16(smb + OFF_Q + 16384 + sw,
                   (const char*)&g_Qlo[((size_t)h * NA + a0 + r) * DKK] + c * 16);
    }
    CP_COMMIT();
    load_tiles(smb, tid, h, a0, 0); CP_COMMIT();
    load_tiles(smb, tid, h, a0, 1); CP_COMMIT();

    float oacc[8][4];
#pragma unroll
    for (int nt = 0; nt < 8; nt++)
#pragma unroll
        for (int e = 0; e < 4; e++) oacc[nt][e] = 0.f;
    float lsum0 = 0.f, lsum1 = 0.f;

    const int qrow = wrow * 16 + (lane & 15);
    const int qcb = (lane >> 4) * 16;
    const int brow = (lane & 7) + ((lane >> 4) << 3);
    const int bkb = ((lane >> 3) & 1) * 16;
    const int er = wrow * 16 + (lane >> 2);
    const int tcol = (lane & 3) * 2;

    CP_WAITG(2);
    __syncthreads();

    for (int bt = 0; bt < NT; bt++) {
        const int s = bt & 1;
        CP_WAITG(1);
        __syncthreads();

        // ---- S(wg half) = Q K^T ----
        float sacc[4][4];
#pragma unroll
        for (int nt = 0; nt < 4; nt++)
#pragma unroll
            for (int e = 0; e < 4; e++) sacc[nt][e] = 0.f;

        const uint32_t kbase = smb + OFF_KS(s);
#pragma unroll
        for (int kc = 0; kc < 4; kc++) {
            unsigned qh[4], ql[4];
            uint32_t qsw = sw128(qrow * 128 + kc * 32 + qcb);
            LDSM4(qh[0], qh[1], qh[2], qh[3], smb + OFF_Q + qsw);
            LDSM4(ql[0], ql[1], ql[2], ql[3], smb + OFF_Q + 16384 + qsw);
#pragma unroll
            for (int ngl = 0; ngl < 2; ngl++) {
                const int ng = wg * 2 + ngl;
                unsigned bh[4], bl[4];
                uint32_t sw = sw128((ng * 16 + brow) * 128 + kc * 32 + bkb);
                LDSM4(bh[0], bh[1], bh[2], bh[3], kbase + sw);
                LDSM4(bl[0], bl[1], bl[2], bl[3], kbase + 8192 + sw);
                mma16816(sacc[2 * ngl], qh, &bh[0]);
                mma16816(sacc[2 * ngl + 1], qh, &bh[2]);
                mma16816(sacc[2 * ngl], ql, &bh[0]);
                mma16816(sacc[2 * ngl + 1], ql, &bh[2]);
                mma16816(sacc[2 * ngl], qh, &bl[0]);
                mma16816(sacc[2 * ngl + 1], qh, &bl[2]);
            }
        }

        // ---- softmax epilogue (prefused wm) ----
        unsigned pH[2][4], pL[2][4];
        const float* wp0 = (const float*)(sm + OFF_WMS(s)) + er * WMP + wg * 32 + tcol;
        const float* wp1 = wp0 + 8 * WMP;
#pragma unroll
        for (int nt = 0; nt < 4; nt++) {
            float2 w0 = *(const float2*)(wp0 + nt * 8);
            float2 w1 = *(const float2*)(wp1 + nt * 8);
            float t00 = fminf(fmaxf(sacc[nt][0] + w0.x, -10.f), 10.f);
            float t01 = fminf(fmaxf(sacc[nt][1] + w0.y, -10.f), 10.f);
            float t10 = fminf(fmaxf(sacc[nt][2] + w1.x, -10.f), 10.f);
            float t11 = fminf(fmaxf(sacc[nt][3] + w1.y, -10.f), 10.f);
            float p00 = __expf(t00 - 10.f), p01 = __expf(t01 - 10.f);
            float p10 = __expf(t10 - 10.f), p11 = __expf(t11 - 10.f);
            lsum0 += p00 + p01;
            lsum1 += p10 + p11;
            unsigned h0, l0, h1, l1;
            cvt_pack(p00, p01, h0, l0);
            cvt_pack(p10, p11, h1, l1);
            int kt = nt >> 1, j = (nt & 1) * 2;
            pH[kt][j] = h0; pH[kt][j + 1] = h1;
            pL[kt][j] = l0; pL[kt][j + 1] = l1;
        }

        // ---- O += P(wg half) V(wg keys) ----
        const uint32_t vbase = smb + OFF_VS(s);
#pragma unroll
        for (int ktl = 0; ktl < 2; ktl++) {
            const int kt = wg * 2 + ktl;
#pragma unroll
            for (int ng = 0; ng < 4; ng++) {
                unsigned bh[4], bl[4];
                uint32_t sw = sw128((ng * 16 + brow) * 128 + kt * 32 + bkb);
                LDSM4(bh[0], bh[1], bh[2], bh[3], vbase + sw);
                LDSM4(bl[0], bl[1], bl[2], bl[3], vbase + 8192 + sw);
                mma16816(oacc[2 * ng], pH[ktl], &bh[0]);
                mma16816(oacc[2 * ng + 1], pH[ktl], &bh[2]);
                mma16816(oacc[2 * ng], pL[ktl], &bh[0]);
                mma16816(oacc[2 * ng + 1], pL[ktl], &bh[2]);
                mma16816(oacc[2 * ng], pH[ktl], &bl[0]);
                mma16816(oacc[2 * ng + 1], pH[ktl], &bl[2]);
            }
        }

        __syncthreads();
        if (bt + 2 < NT) load_tiles(smb, tid, h, a0, bt + 2);
        CP_COMMIT();
    }

    // ---- combine the two warpgroup halves ----
    lsum0 += __shfl_xor_sync(0xFFFFFFFFu, lsum0, 1);
    lsum0 += __shfl_xor_sync(0xFFFFFFFFu, lsum0, 2);
    lsum1 += __shfl_xor_sync(0xFFFFFFFFu, lsum1, 1);
    lsum1 += __shfl_xor_sync(0xFFFFFFFFu, lsum1, 2);

    float* sls = (float*)(sm + OFF_LS);
    float* soc = (float*)(sm + OFF_OC);
    if ((lane & 3) == 0) {
        sls[wg * 128 + er] = lsum0;
        sls[wg * 128 + er + 8] = lsum1;
    }
    if (wg == 1) {
#pragma unroll
        for (int ng = 0; ng < 4; ng++)
#pragma unroll
            for (int j = 0; j < 2; j++) {
                int c = ng * 16 + j * 8 + tcol;
                *(float2*)&soc[er * 64 + c] =
                    make_float2(oacc[2 * ng + j][0], oacc[2 * ng + j][1]);
                *(float2*)&soc[(er + 8) * 64 + c] =
                    make_float2(oacc[2 * ng + j][2], oacc[2 * ng + j][3]);
            }
    }
    __syncthreads();
    if (wg == 0) {
        const float inv0 = 0.25f / (sls[er] + sls[128 + er]);
        const float inv1 = 0.25f / (sls[er + 8] + sls[128 + er + 8]);
        float* d0 = &g_ctx[((size_t)h * NA + a0 + er) * DKK + tcol];
        float* d1 = d0 + 8 * DKK;
#pragma unroll
        for (int ng = 0; ng < 4; ng++)
#pragma unroll
            for (int j = 0; j < 2; j++) {
                int c = ng * 16 + j * 8 + tcol;
                float2 u0 = *(float2*)&soc[er * 64 + c];
                float2 u1 = *(float2*)&soc[(er + 8) * 64 + c];
                *(float2*)(d0 + ng * 16 + j * 8) =
                    make_float2((oacc[2 * ng + j][0] + u0.x) * inv0,
                                (oacc[2 * ng + j][1] + u0.y) * inv0);
                *(float2*)(d1 + ng * 16 + j * 8) =
                    make_float2((oacc[2 * ng + j][2] + u1.x) * inv1,
                                (oacc[2 * ng + j][3] + u1.y) * inv1);
            }
    }
}

// ---------------- final reduce ----------------
__global__ void __launch_bounds__(256) reduce_kernel(float* __restrict__ out) {
    int idx = blockIdx.x * 256 + threadIdx.x;
    const int NC = NA * DKK;
    if (idx < NC) {
        out[idx] = g_ctx[idx] + g_ctx[idx + NC] + g_ctx[idx + 2 * NC] + g_ctx[idx + 3 * NC];
    } else if (idx < NC + NA) {
        out[idx] = 1.0f;
    }
}

// ---------------- launch ----------------
extern "C" void kernel_launch(void* const* d_in, const int* in_sizes, int n_in,
                              void* d_out, int out_size)
{
    const float* a_z    = (const float*)d_in[0];
    const float* bv_z   = (const float*)d_in[1];
    const void*  mask   = d_in[2];
    const float* weight = (const float*)d_in[3];
    const float* Wq     = (const float*)d_in[4];
    const float* Wk     = (const float*)d_in[5];
    const float* Wv     = (const float*)d_in[6];
    float* out = (float*)d_out;

    detect_mask_kind<<<1, 1024>>>((const unsigned int*)mask);
    prep_wm<<<8192, 256>>>((const float4*)weight, mask);

    cudaFuncSetAttribute(proj_mma, cudaFuncAttributeMaxDynamicSharedMemorySize, PJ_SMEM);
    proj_mma<<<dim3(NA / 128, 2, 3), 256, PJ_SMEM>>>(a_z, bv_z, Wq, Wk, Wv);

    cudaFuncSetAttribute(attn_kernel, cudaFuncAttributeMaxDynamicSharedMemorySize, SMEM_BYTES);
    attn_kernel<<<dim3(NA / BM, HH), 512, SMEM_BYTES>>>();

    reduce_kernel<<<(NA * DKK + NA + 255) / 256, 256>>>(out);
}

// round 7
// speedup vs baseline: 5.7699x; 1.1676x over previous
#include <cuda_runtime.h>
#include <cuda_bf16.h>
#include <cuda_fp16.h>
#include <cstdint>

#define NA 4096
#define NB 4096
#define DD 256
#define HH 4
#define DKK 64
#define BM 128
#define BC 64
#define NT (NB / BC)

// ---------------- device scratch ----------------
__device__ __half g_Qhi[HH * NA * DKK];
__device__ __half g_Qlo[HH * NA * DKK];
__device__ __half g_Kh[HH * NB * DKK];
__device__ __half g_Vth[HH * DKK * NB];          // [h][dk][token]
__device__ float g_wm[(size_t)NA * NB];          // san(weight) + (mask?0:-1e4)
__device__ float g_ctx[HH * NA * DKK];
__device__ int g_mask_kind;

// ---------------- helpers ----------------
__device__ __forceinline__ uint32_t smem_u32(const void* p) {
    uint32_t a;
    asm("{ .reg .u64 t; cvta.to.shared.u64 t, %1; cvt.u32.u64 %0, t; }" : "=r"(a) : "l"(p));
    return a;
}
__device__ __forceinline__ uint32_t sw128(uint32_t o) { return o ^ ((o >> 3) & 0x70); }

#define CP_ASYNC16(dst, src) \
    asm volatile("cp.async.cg.shared.global [%0], [%1], 16;\n" :: "r"(dst), "l"(src))
#define CP_COMMIT()  asm volatile("cp.async.commit_group;\n" ::: "memory")
#define CP_WAITG(n)  asm volatile("cp.async.wait_group %0;\n" :: "n"(n) : "memory")

#define LDSM4(r0, r1, r2, r3, a) \
    asm volatile("ldmatrix.sync.aligned.m8n8.x4.shared.b16 {%0,%1,%2,%3}, [%4];" \
                 : "=r"(r0), "=r"(r1), "=r"(r2), "=r"(r3) : "r"(a))

// bf16 mma (projection kernel)
__device__ __forceinline__ void mma_bf16(float* c, const unsigned* a, const unsigned* b) {
    asm volatile(
        "mma.sync.aligned.m16n8k16.row.col.f32.bf16.bf16.f32 "
        "{%0,%1,%2,%3}, {%4,%5,%6,%7}, {%8,%9}, {%0,%1,%2,%3};\n"
        : "+f"(c[0]), "+f"(c[1]), "+f"(c[2]), "+f"(c[3])
        : "r"(a[0]), "r"(a[1]), "r"(a[2]), "r"(a[3]), "r"(b[0]), "r"(b[1]));
}
// fp16 mma (attention kernel)
__device__ __forceinline__ void mma_f16(float* c, const unsigned* a, const unsigned* b) {
    asm volatile(
        "mma.sync.aligned.m16n8k16.row.col.f32.f16.f16.f32 "
        "{%0,%1,%2,%3}, {%4,%5,%6,%7}, {%8,%9}, {%0,%1,%2,%3};\n"
        : "+f"(c[0]), "+f"(c[1]), "+f"(c[2]), "+f"(c[3])
        : "r"(a[0]), "r"(a[1]), "r"(a[2]), "r"(a[3]), "r"(b[0]), "r"(b[1]));
}

// bf16 hi/lo split pack (projection internals)
__device__ __forceinline__ void cvt_pack_bf(float x0, float x1, unsigned& hi, unsigned& lo) {
    __nv_bfloat16 h0 = __float2bfloat16(x0), h1 = __float2bfloat16(x1);
    __nv_bfloat16 l0 = __float2bfloat16(x0 - __bfloat162float(h0));
    __nv_bfloat16 l1 = __float2bfloat16(x1 - __bfloat162float(h1));
    hi = ((unsigned)__bfloat16_as_ushort(h1) << 16) | (unsigned)__bfloat16_as_ushort(h0);
    lo = ((unsigned)__bfloat16_as_ushort(l1) << 16) | (unsigned)__bfloat16_as_ushort(l0);
}
// fp16 hi/lo split pack
__device__ __forceinline__ void cvt_pack_h(float x0, float x1, unsigned& hi, unsigned& lo) {
    __half h0 = __float2half_rn(x0), h1 = __float2half_rn(x1);
    __half l0 = __float2half_rn(x0 - __half2float(h0));
    __half l1 = __float2half_rn(x1 - __half2float(h1));
    hi = ((unsigned)__half_as_ushort(h1) << 16) | (unsigned)__half_as_ushort(h0);
    lo = ((unsigned)__half_as_ushort(l1) << 16) | (unsigned)__half_as_ushort(l0);
}
// fp16 single pack
__device__ __forceinline__ unsigned pack_h(float x0, float x1) {
    return ((unsigned)__half_as_ushort(__float2half_rn(x1)) << 16)
         | (unsigned)__half_as_ushort(__float2half_rn(x0));
}

__device__ __forceinline__ float san(float x) {
    if (isnan(x)) return 0.f;
    if (isinf(x)) return x > 0.f ? 1.f : -1.f;
    return x;
}

// ---------------- mask dtype detector ----------------
__global__ void detect_mask_kind(const unsigned int* __restrict__ m) {
    __shared__ int s_i32, s_f32;
    if (threadIdx.x == 0) { s_i32 = 1; s_f32 = 1; }
    __syncthreads();
    int ok_i = 1, ok_f = 1;
    for (int i = threadIdx.x; i < 4096; i += 1024) {
        unsigned v = m[i];
        ok_i &= (v <= 1u);
        ok_f &= (v == 0u || v == 0x3F800000u);
    }
    if (!ok_i) atomicAnd(&s_i32, 0);
    if (!ok_f) atomicAnd(&s_f32, 0);
    __syncthreads();
    if (threadIdx.x == 0) g_mask_kind = s_i32 ? 1 : (s_f32 ? 2 : 0);
}

// ---------------- prep: fold sanitize + mask into weight ----------------
__global__ void __launch_bounds__(256) prep_wm(const float4* __restrict__ w4,
                                               const void* __restrict__ mraw) {
    const int kind = g_mask_kind;
    const size_t n4 = (size_t)NA * NB / 4;
    size_t i = (size_t)blockIdx.x * 256 + threadIdx.x;
    const size_t stride = (size_t)gridDim.x * 256;
    for (; i < n4; i += stride) {
        float4 w = w4[i];
        w.x = san(w.x); w.y = san(w.y); w.z = san(w.z); w.w = san(w.w);
        int b0, b1, b2, b3;
        if (kind == 1) {
            int4 m = ((const int4*)mraw)[i];
            b0 = m.x != 0; b1 = m.y != 0; b2 = m.z != 0; b3 = m.w != 0;
        } else if (kind == 2) {
            float4 m = ((const float4*)mraw)[i];
            b0 = m.x != 0.f; b1 = m.y != 0.f; b2 = m.z != 0.f; b3 = m.w != 0.f;
        } else {
            uchar4 m = ((const uchar4*)mraw)[i];
            b0 = m.x != 0; b1 = m.y != 0; b2 = m.z != 0; b3 = m.w != 0;
        }
        float4 o;
        o.x = w.x + (b0 ? 0.f : -10000.f);
        o.y = w.y + (b1 ? 0.f : -10000.f);
        o.z = w.z + (b2 ? 0.f : -10000.f);
        o.w = w.w + (b3 ? 0.f : -10000.f);
        ((float4*)g_wm)[i] = o;
    }
}

// ---------------- projections via bf16 3-term mma; outputs fp16 ----------------
#define PJ_XF(s)  ((s) * 32768)
#define PJ_WF(s)  (65536 + (s) * 32768)
#define PJ_XHI 131072
#define PJ_XLO 147456
#define PJ_WHI 163840
#define PJ_WLO 180224
#define PJ_SMEM 196608
#define VT_PITCH 132

__global__ void __launch_bounds__(256, 1) proj_mma(
    const float* __restrict__ a_z, const float* __restrict__ bv_z,
    const float* __restrict__ Wq, const float* __restrict__ Wk, const float* __restrict__ Wv)
{
    extern __shared__ char sm[];
    const uint32_t smb = smem_u32(sm);
    const int tid = threadIdx.x, wid = tid >> 5, lane = tid & 31;
    const int mat = blockIdx.z;
    const int m0 = blockIdx.x * 128, nb = blockIdx.y * 128;
    const float* X = (mat == 0) ? a_z : bv_z;
    const float* W = (mat == 0) ? Wq : (mat == 1 ? Wk : Wv);

    auto load_chunk = [&](int c) {
        const int s = c & 1;
        for (int i = tid; i < 2048; i += 256) {
            int r = i >> 4, q = i & 15;
            CP_ASYNC16(smb + PJ_XF(s) + r * 256 + q * 16,
                       (const char*)&X[(size_t)(m0 + r) * DD + c * 64] + q * 16);
            CP_ASYNC16(smb + PJ_WF(s) + r * 256 + q * 16,
                       (const char*)&W[(size_t)(nb + r) * DD + c * 64] + q * 16);
        }
    };
    load_chunk(0); CP_COMMIT();
    load_chunk(1); CP_COMMIT();

    float oacc[16][4];
#pragma unroll
    for (int nt = 0; nt < 16; nt++)
#pragma unroll
        for (int e = 0; e < 4; e++) oacc[nt][e] = 0.f;

    const int arow = wid * 16 + (lane & 15);
    const int akb = (lane >> 4) * 16;
    const int brow = (lane & 7) + ((lane >> 4) << 3);
    const int bkb = ((lane >> 3) & 1) * 16;

    for (int c = 0; c < 4; c++) {
        const int s = c & 1;
        CP_WAITG(1);
        __syncthreads();
#pragma unroll
        for (int j = 0; j < 16; j++) {
            int p = tid + j * 256;
            int r = p >> 5, cp2 = p & 31;
            float2 xv = *(const float2*)(sm + PJ_XF(s) + r * 256 + cp2 * 8);
            float2 wv = *(const float2*)(sm + PJ_WF(s) + r * 256 + cp2 * 8);
            unsigned hi, lo;
            cvt_pack_bf(san(xv.x), san(xv.y), hi, lo);
            uint32_t off = sw128(r * 128 + cp2 * 4);
            *(uint32_t*)(sm + PJ_XHI + off) = hi;
            *(uint32_t*)(sm + PJ_XLO + off) = lo;
            cvt_pack_bf(wv.x, wv.y, hi, lo);
            *(uint32_t*)(sm + PJ_WHI + off) = hi;
            *(uint32_t*)(sm + PJ_WLO + off) = lo;
        }
        __syncthreads();
#pragma unroll
        for (int kc = 0; kc < 4; kc++) {
            unsigned ah[4], al[4];
            uint32_t asw = sw128(arow * 128 + kc * 32 + akb);
            LDSM4(ah[0], ah[1], ah[2], ah[3], smb + PJ_XHI + asw);
            LDSM4(al[0], al[1], al[2], al[3], smb + PJ_XLO + asw);
#pragma unroll
            for (int ng = 0; ng < 8; ng++) {
                unsigned bh[4], bl[4];
                uint32_t bsw = sw128((ng * 16 + brow) * 128 + kc * 32 + bkb);
                LDSM4(bh[0], bh[1], bh[2], bh[3], smb + PJ_WHI + bsw);
                LDSM4(bl[0], bl[1], bl[2], bl[3], smb + PJ_WLO + bsw);
                mma_bf16(oacc[2 * ng], ah, &bh[0]);
                mma_bf16(oacc[2 * ng + 1], ah, &bh[2]);
                mma_bf16(oacc[2 * ng], al, &bh[0]);
                mma_bf16(oacc[2 * ng + 1], al, &bh[2]);
                mma_bf16(oacc[2 * ng], ah, &bl[0]);
                mma_bf16(oacc[2 * ng + 1], ah, &bl[2]);
            }
        }
        __syncthreads();
        if (c + 2 < 4) load_chunk(c + 2);
        CP_COMMIT();
    }

    const int er = wid * 16 + (lane >> 2);
    const int tcol = (lane & 3) * 2;

    if (mat == 2) {
        // transpose V tile through smem, then fp16 vectorized stores
        float* smf = (float*)sm;
#pragma unroll
        for (int nt = 0; nt < 16; nt++)
#pragma unroll
            for (int hf = 0; hf < 2; hf++) {
                int row = er + hf * 8;
                int col = nt * 8 + tcol;
                smf[(col) * VT_PITCH + row] = oacc[nt][2 * hf];
                smf[(col + 1) * VT_PITCH + row] = oacc[nt][2 * hf + 1];
            }
        __syncthreads();
        for (int idx = tid; idx < 128 * 32; idx += 256) {
            int c = idx >> 5, tb = idx & 31;
            const float* src = &smf[c * VT_PITCH + tb * 4];
            unsigned u0 = pack_h(src[0], src[1]);
            unsigned u1 = pack_h(src[2], src[3]);
            int col = nb + c;
            int head = col >> 6, cc = col & 63;
            size_t o = (size_t)(head * DKK + cc) * NB + m0 + tb * 4;
            *(uint2*)&g_Vth[o] = make_uint2(u0, u1);
        }
    } else if (mat == 0) {
#pragma unroll
        for (int nt = 0; nt < 16; nt++)
#pragma unroll
            for (int hf = 0; hf < 2; hf++) {
                int row = m0 + er + hf * 8;
                int col = nb + nt * 8 + tcol;
                int head = col >> 6, cc = col & 63;
                float x0 = oacc[nt][2 * hf] * 0.125f;
                float x1 = oacc[nt][2 * hf + 1] * 0.125f;
                unsigned hi, lo;
                cvt_pack_h(x0, x1, hi, lo);
                size_t o = (size_t)(head * NA + row) * DKK + cc;
                *(unsigned*)&g_Qhi[o] = hi;
                *(unsigned*)&g_Qlo[o] = lo;
            }
    } else {
#pragma unroll
        for (int nt = 0; nt < 16; nt++)
#pragma unroll
            for (int hf = 0; hf < 2; hf++) {
                int row = m0 + er + hf * 8;
                int col = nb + nt * 8 + tcol;
                int head = col >> 6, cc = col & 63;
                unsigned u = pack_h(oacc[nt][2 * hf], oacc[nt][2 * hf + 1]);
                size_t o = (size_t)(head * NA + row) * DKK + cc;
                *(unsigned*)&g_Kh[o] = u;
            }
    }
}

// ---------------- attention smem layout ----------------
#define WMP 76
#define OFF_Q 0
#define OFF_KS(s)  (32768 + (s) * 8192)
#define OFF_VS(s)  (49152 + (s) * 8192)
#define OFF_WMS(s) (65536 + (s) * 38912)
#define OFF_OC 32768      // O-combine (reuses K/V stages after mainloop, 32KB)
#define OFF_LS 0          // lsum combine (reuses Q region)
#define SMEM_BYTES 143360

__device__ __forceinline__ void load_tiles(uint32_t smb, int tid, int h, int a0, int bt) {
    const int s = bt & 1, b0 = bt * BC;
    {
        int r = tid >> 3, c = tid & 7;              // 512 threads = 64 rows x 8 chunks
        uint32_t sw = sw128(r * 128 + c * 16);
        CP_ASYNC16(smb + OFF_KS(s) + sw,
                   (const char*)&g_Kh[((size_t)h * NB + b0 + r) * DKK] + c * 16);
        CP_ASYNC16(smb + OFF_VS(s) + sw,
                   (const char*)&g_Vth[((size_t)(h * DKK + r)) * NB + b0] + c * 16);
    }
    for (int i = tid; i < 2048; i += 512) {
        int r = i >> 4, c = i & 15;
        CP_ASYNC16(smb + OFF_WMS(s) + r * (WMP * 4) + c * 16,
                   (const char*)&g_wm[(size_t)(a0 + r) * NB + b0] + c * 16);
    }
}

// ---------------- attention mainloop: 512 threads, fp16 2-term ----------------
__global__ void __launch_bounds__(512, 1) attn_kernel() {
    extern __shared__ char sm[];
    const uint32_t smb = smem_u32(sm);
    const int tid = threadIdx.x, wid = tid >> 5, lane = tid & 31;
    const int wg = wid >> 3, wrow = wid & 7;
    const int a0 = blockIdx.x * BM, h = blockIdx.y;

    for (int i = tid; i < 1024; i += 512) {
        int r = i >> 3, c = i & 7;
        uint32_t sw = sw128(r * 128 + c * 16);
        CP_ASYNC16(smb + OFF_Q + sw,
                   (const char*)&g_Qhi[((size_t)h * NA + a0 + r) * DKK] + c * 16);
        CP_ASYNC16(smb + OFF_Q + 16384 + sw,
                   (const char*)&g_Qlo[((size_t)h * NA + a0 + r) * DKK] + c * 16);
    }
    CP_COMMIT();
    load_tiles(smb, tid, h, a0, 0); CP_COMMIT();
    load_tiles(smb, tid, h, a0, 1); CP_COMMIT();

    float oacc[8][4];
#pragma unroll
    for (int nt = 0; nt < 8; nt++)
#pragma unroll
        for (int e = 0; e < 4; e++) oacc[nt][e] = 0.f;
    float lsum0 = 0.f, lsum1 = 0.f;

    const int qrow = wrow * 16 + (lane & 15);
    const int qcb = (lane >> 4) * 16;
    const int brow = (lane & 7) + ((lane >> 4) << 3);
    const int bkb = ((lane >> 3) & 1) * 16;
    const int er = wrow * 16 + (lane >> 2);
    const int tcol = (lane & 3) * 2;

    CP_WAITG(2);
    __syncthreads();

    for (int bt = 0; bt < NT; bt++) {
        const int s = bt & 1;
        CP_WAITG(1);
        __syncthreads();

        // ---- S(wg half) = Q K^T : (qh+ql)·kh ----
        float sacc[4][4];
#pragma unroll
        for (int nt = 0; nt < 4; nt++)
#pragma unroll
            for (int e = 0; e < 4; e++) sacc[nt][e] = 0.f;

        const uint32_t kbase = smb + OFF_KS(s);
#pragma unroll
        for (int kc = 0; kc < 4; kc++) {
            unsigned qh[4], ql[4];
            uint32_t qsw = sw128(qrow * 128 + kc * 32 + qcb);
            LDSM4(qh[0], qh[1], qh[2], qh[3], smb + OFF_Q + qsw);
            LDSM4(ql[0], ql[1], ql[2], ql[3], smb + OFF_Q + 16384 + qsw);
#pragma unroll
            for (int ngl = 0; ngl < 2; ngl++) {
                const int ng = wg * 2 + ngl;
                unsigned bh[4];
                uint32_t sw = sw128((ng * 16 + brow) * 128 + kc * 32 + bkb);
                LDSM4(bh[0], bh[1], bh[2], bh[3], kbase + sw);
                mma_f16(sacc[2 * ngl], qh, &bh[0]);
                mma_f16(sacc[2 * ngl + 1], qh, &bh[2]);
                mma_f16(sacc[2 * ngl], ql, &bh[0]);
                mma_f16(sacc[2 * ngl + 1], ql, &bh[2]);
            }
        }

        // ---- softmax epilogue (prefused wm), P split to fp16 hi/lo ----
        unsigned pH[2][4], pL[2][4];
        const float* wp0 = (const float*)(sm + OFF_WMS(s)) + er * WMP + wg * 32 + tcol;
        const float* wp1 = wp0 + 8 * WMP;
#pragma unroll
        for (int nt = 0; nt < 4; nt++) {
            float2 w0 = *(const float2*)(wp0 + nt * 8);
            float2 w1 = *(const float2*)(wp1 + nt * 8);
            float t00 = fminf(fmaxf(sacc[nt][0] + w0.x, -10.f), 10.f);
            float t01 = fminf(fmaxf(sacc[nt][1] + w0.y, -10.f), 10.f);
            float t10 = fminf(fmaxf(sacc[nt][2] + w1.x, -10.f), 10.f);
            float t11 = fminf(fmaxf(sacc[nt][3] + w1.y, -10.f), 10.f);
            float p00 = __expf(t00 - 10.f), p01 = __expf(t01 - 10.f);
            float p10 = __expf(t10 - 10.f), p11 = __expf(t11 - 10.f);
            lsum0 += p00 + p01;
            lsum1 += p10 + p11;
            unsigned h0, l0, h1, l1;
            cvt_pack_h(p00, p01, h0, l0);
            cvt_pack_h(p10, p11, h1, l1);
            int kt = nt >> 1, j = (nt & 1) * 2;
            pH[kt][j] = h0; pH[kt][j + 1] = h1;
            pL[kt][j] = l0; pL[kt][j + 1] = l1;
        }

        // ---- O += P(wg half) V(wg keys) : (ph+pl)·vh ----
        const uint32_t vbase = smb + OFF_VS(s);
#pragma unroll
        for (int ktl = 0; ktl < 2; ktl++) {
            const int kt = wg * 2 + ktl;
#pragma unroll
            for (int ng = 0; ng < 4; ng++) {
                unsigned bh[4];
                uint32_t sw = sw128((ng * 16 + brow) * 128 + kt * 32 + bkb);
                LDSM4(bh[0], bh[1], bh[2], bh[3], vbase + sw);
                mma_f16(oacc[2 * ng], pH[ktl], &bh[0]);
                mma_f16(oacc[2 * ng + 1], pH[ktl], &bh[2]);
                mma_f16(oacc[2 * ng], pL[ktl], &bh[0]);
                mma_f16(oacc[2 * ng + 1], pL[ktl], &bh[2]);
            }
        }

        __syncthreads();
        if (bt + 2 < NT) load_tiles(smb, tid, h, a0, bt + 2);
        CP_COMMIT();
    }

    // ---- combine the two warpgroup halves ----
    lsum0 += __shfl_xor_sync(0xFFFFFFFFu, lsum0, 1);
    lsum0 += __shfl_xor_sync(0xFFFFFFFFu, lsum0, 2);
    lsum1 += __shfl_xor_sync(0xFFFFFFFFu, lsum1, 1);
    lsum1 += __shfl_xor_sync(0xFFFFFFFFu, lsum1, 2);

    float* sls = (float*)(sm + OFF_LS);
    float* soc = (float*)(sm + OFF_OC);
    if ((lane & 3) == 0) {
        sls[wg * 128 + er] = lsum0;
        sls[wg * 128 + er + 8] = lsum1;
    }
    if (wg == 1) {
#pragma unroll
        for (int ng = 0; ng < 4; ng++)
#pragma unroll
            for (int j = 0; j < 2; j++) {
                int c = ng * 16 + j * 8 + tcol;
                *(float2*)&soc[er * 64 + c] =
                    make_float2(oacc[2 * ng + j][0], oacc[2 * ng + j][1]);
                *(float2*)&soc[(er + 8) * 64 + c] =
                    make_float2(oacc[2 * ng + j][2], oacc[2 * ng + j][3]);
            }
    }
    __syncthreads();
    if (wg == 0) {
        const float inv0 = 0.25f / (sls[er] + sls[128 + er]);
        const float inv1 = 0.25f / (sls[er + 8] + sls[128 + er + 8]);
        float* d0 = &g_ctx[((size_t)h * NA + a0 + er) * DKK + tcol];
        float* d1 = d0 + 8 * DKK;
#pragma unroll
        for (int ng = 0; ng < 4; ng++)
#pragma unroll
            for (int j = 0; j < 2; j++) {
                int c = ng * 16 + j * 8 + tcol;
                float2 u0 = *(float2*)&soc[er * 64 + c];
                float2 u1 = *(float2*)&soc[(er + 8) * 64 + c];
                *(float2*)(d0 + ng * 16 + j * 8) =
                    make_float2((oacc[2 * ng + j][0] + u0.x) * inv0,
                                (oacc[2 * ng + j][1] + u0.y) * inv0);
                *(float2*)(d1 + ng * 16 + j * 8) =
                    make_float2((oacc[2 * ng + j][2] + u1.x) * inv1,
                                (oacc[2 * ng + j][3] + u1.y) * inv1);
            }
    }
}

// ---------------- final reduce ----------------
__global__ void __launch_bounds__(256) reduce_kernel(float* __restrict__ out) {
    int idx = blockIdx.x * 256 + threadIdx.x;
    const int NC = NA * DKK;
    if (idx < NC) {
        out[idx] = g_ctx[idx] + g_ctx[idx + NC] + g_ctx[idx + 2 * NC] + g_ctx[idx + 3 * NC];
    } else if (idx < NC + NA) {
        out[idx] = 1.0f;
    }
}

// ---------------- launch ----------------
extern "C" void kernel_launch(void* const* d_in, const int* in_sizes, int n_in,
                              void* d_out, int out_size)
{
    const float* a_z    = (const float*)d_in[0];
    const float* bv_z   = (const float*)d_in[1];
    const void*  mask   = d_in[2];
    const float* weight = (const float*)d_in[3];
    const float* Wq     = (const float*)d_in[4];
    const float* Wk     = (const float*)d_in[5];
    const float* Wv     = (const float*)d_in[6];
    float* out = (float*)d_out;

    detect_mask_kind<<<1, 1024>>>((const unsigned int*)mask);
    prep_wm<<<8192, 256>>>((const float4*)weight, mask);

    cudaFuncSetAttribute(proj_mma, cudaFuncAttributeMaxDynamicSharedMemorySize, PJ_SMEM);
    proj_mma<<<dim3(NA / 128, 2, 3), 256, PJ_SMEM>>>(a_z, bv_z, Wq, Wk, Wv);

    cudaFuncSetAttribute(attn_kernel, cudaFuncAttributeMaxDynamicSharedMemorySize, SMEM_BYTES);
    attn_kernel<<<dim3(NA / BM, HH), 512, SMEM_BYTES>>>();

    reduce_kernel<<<(NA * DKK + NA + 255) / 256, 256>>>(out);
}